// round 4
// baseline (speedup 1.0000x reference)
#include <cuda_runtime.h>
#include <cstdint>

// Shapes (fixed for this problem)
#define BB 64
#define TT 512
#define DD 256
#define HH 512
#define G4H 2048           // 4*H
#define MROWS 32768        // B*T
#define OUT0 16777216      // B*T*H

// ---------------- device scratch (static allocation; no cudaMalloc) -------
__device__ float g_xw[2][MROWS][G4H];   // x@W+b, row r = b*T + t   (512 MB)
__device__ float g_ut[2][G4H][HH];      // U transposed: Ut[col][k] (8 MB)
__device__ float g_h[2][2][BB][HH];     // [dir][pingpong][b][h]
__device__ float g_c[2][BB][HH];        // [dir][b][h]

__device__ __forceinline__ float sigm(float x) {
    return 1.0f / (1.0f + __expf(-x));
}

// ---------------- state init (must re-zero every launch: replay-safe) ----
__global__ void init_state_kernel() {
    int i = blockIdx.x * blockDim.x + threadIdx.x;
    float* h = &g_h[0][0][0][0];
    float* c = &g_c[0][0][0];
    if (i < 2 * 2 * BB * HH) h[i] = 0.0f;
    if (i < 2 * BB * HH)     c[i] = 0.0f;
}

// ---------------- transpose U: Ut[dir][col][k] = U[k][col] ---------------
__global__ void transu_kernel(const float* __restrict__ Uf,
                              const float* __restrict__ Ub) {
    __shared__ float tile[32][33];
    const float* U = blockIdx.z ? Ub : Uf;
    int c0 = blockIdx.x * 32, k0 = blockIdx.y * 32;
    tile[threadIdx.y][threadIdx.x] =
        U[(size_t)(k0 + threadIdx.y) * G4H + c0 + threadIdx.x];
    __syncthreads();
    g_ut[blockIdx.z][c0 + threadIdx.y][k0 + threadIdx.x] =
        tile[threadIdx.x][threadIdx.y];
}

// ---------------- input projection: g_xw = x @ W + b ---------------------
// M=32768, N=2048, K=256.  128x128 tile, 8x8 microtile, 256 threads.
__global__ __launch_bounds__(256, 2) void proj_kernel(
    const float* __restrict__ x,
    const float* __restrict__ Wf, const float* __restrict__ bf,
    const float* __restrict__ Wb, const float* __restrict__ bb) {
    __shared__ float As[2][8][132];   // [k][row], padded
    __shared__ float Bs[2][8][128];   // [k][col]

    const int mt = blockIdx.x, nt = blockIdx.y, dir = blockIdx.z;
    const float* W    = dir ? Wb : Wf;
    const float* bias = dir ? bb : bf;
    float* xwout = &g_xw[dir][0][0];

    const int tid = threadIdx.x;
    const int ty = tid >> 4;       // 0..15 row group
    const int tx = tid & 15;       // 0..15 col group

    // loaders
    const int arow = tid >> 1, ak = (tid & 1) * 4;          // A: 128 rows x 8 k
    const int brow = tid >> 5, bcol = (tid & 31) * 4;       // B: 8 k x 128 cols
    const float* aptr = x + (size_t)(mt * 128 + arow) * DD + ak;
    const float* bptr = W + (size_t)brow * G4H + nt * 128 + bcol;

    float acc[8][8];
#pragma unroll
    for (int i = 0; i < 8; i++)
#pragma unroll
        for (int j = 0; j < 8; j++) acc[i][j] = 0.0f;

    float4 areg = *(const float4*)(aptr);
    float4 breg = *(const float4*)(bptr);

    for (int c = 0; c < 32; ++c) {
        const int buf = c & 1;
        As[buf][ak + 0][arow] = areg.x;
        As[buf][ak + 1][arow] = areg.y;
        As[buf][ak + 2][arow] = areg.z;
        As[buf][ak + 3][arow] = areg.w;
        *(float4*)&Bs[buf][brow][bcol] = breg;
        __syncthreads();
        if (c < 31) {
            areg = *(const float4*)(aptr + (c + 1) * 8);
            breg = *(const float4*)(bptr + (size_t)(c + 1) * 8 * G4H);
        }
#pragma unroll
        for (int kk = 0; kk < 8; ++kk) {
            float4 a0 = *(const float4*)&As[buf][kk][ty * 8];
            float4 a1 = *(const float4*)&As[buf][kk][ty * 8 + 4];
            float4 b0 = *(const float4*)&Bs[buf][kk][tx * 8];
            float4 b1 = *(const float4*)&Bs[buf][kk][tx * 8 + 4];
            float av[8] = {a0.x, a0.y, a0.z, a0.w, a1.x, a1.y, a1.z, a1.w};
            float bv[8] = {b0.x, b0.y, b0.z, b0.w, b1.x, b1.y, b1.z, b1.w};
#pragma unroll
            for (int i = 0; i < 8; i++)
#pragma unroll
                for (int j = 0; j < 8; j++) acc[i][j] += av[i] * bv[j];
        }
        __syncthreads();
    }

    // epilogue: add bias, store (vectorized)
    float bv0[8];
#pragma unroll
    for (int j = 0; j < 8; j++) bv0[j] = bias[nt * 128 + tx * 8 + j];
#pragma unroll
    for (int i = 0; i < 8; i++) {
        const size_t row = (size_t)(mt * 128 + ty * 8 + i);
        float* dst = xwout + row * G4H + nt * 128 + tx * 8;
        float4 o0 = make_float4(acc[i][0] + bv0[0], acc[i][1] + bv0[1],
                                acc[i][2] + bv0[2], acc[i][3] + bv0[3]);
        float4 o1 = make_float4(acc[i][4] + bv0[4], acc[i][5] + bv0[5],
                                acc[i][6] + bv0[6], acc[i][7] + bv0[7]);
        *(float4*)(dst)     = o0;
        *(float4*)(dst + 4) = o1;
    }
}

// ---------------- one LSTM timestep (both directions in grid.y) ----------
// CTA: (jt, dir). Owns hidden slice j0..j0+7 => 32 gate cols (i,f,g,o).
// Z[64 x 32] = Xw[t] + H[64 x 512] @ U[512 x cols], then fused gate update.
__global__ __launch_bounds__(256) void step_kernel(int s, float* __restrict__ dout) {
    __shared__ float hs[64][68];    // [k][b], 16B-aligned rows
    __shared__ float us[64][36];    // [k][lc]
    __shared__ float zbuf[64][33];  // [b][lc]

    const int dir = blockIdx.y;
    const int jt  = blockIdx.x;
    const int j0  = jt * 8;
    const int t   = dir ? (TT - 1 - s) : s;
    const int pr  = s & 1;

    const float* __restrict__ hprev = &g_h[dir][pr][0][0];
    float* __restrict__ hnext       = &g_h[dir][pr ^ 1][0][0];
    float* __restrict__ cst         = &g_c[dir][0][0];
    const float* __restrict__ xw    = &g_xw[dir][0][0];
    const float* __restrict__ ut    = &g_ut[dir][0][0];

    const int tid = threadIdx.x;
    const int ty = tid & 15;   // row group (b = ty*4 + i)
    const int tx = tid >> 4;   // col pair (lc = tx*2 + j)

    // loader mappings
    const int hb  = tid >> 2;          // 0..63 (batch row)
    const int hk0 = (tid & 3) * 16;    // k base within chunk
    const int ulc = tid & 31;          // 0..31 local col
    const int ukb = tid >> 5;          // 0..7  (8 k's each)
    const int ugcol = ((ulc >> 3) * HH) + j0 + (ulc & 7);
    const float* hsrc = hprev + hb * HH + hk0;
    const float* usrc = ut + (size_t)ugcol * HH + ukb * 8;

    float4 hreg[4], ureg[2];
#pragma unroll
    for (int q = 0; q < 4; q++) hreg[q] = *(const float4*)(hsrc + q * 4);
#pragma unroll
    for (int q = 0; q < 2; q++) ureg[q] = *(const float4*)(usrc + q * 4);

    float acc[4][2] = {{0.f, 0.f}, {0.f, 0.f}, {0.f, 0.f}, {0.f, 0.f}};

    for (int c = 0; c < 8; ++c) {
        __syncthreads();  // previous chunk's compute done; smem free
#pragma unroll
        for (int q = 0; q < 4; q++) {
            hs[hk0 + q * 4 + 0][hb] = hreg[q].x;
            hs[hk0 + q * 4 + 1][hb] = hreg[q].y;
            hs[hk0 + q * 4 + 2][hb] = hreg[q].z;
            hs[hk0 + q * 4 + 3][hb] = hreg[q].w;
        }
#pragma unroll
        for (int q = 0; q < 2; q++) {
            us[ukb * 8 + q * 4 + 0][ulc] = ureg[q].x;
            us[ukb * 8 + q * 4 + 1][ulc] = ureg[q].y;
            us[ukb * 8 + q * 4 + 2][ulc] = ureg[q].z;
            us[ukb * 8 + q * 4 + 3][ulc] = ureg[q].w;
        }
        __syncthreads();
        if (c < 7) {  // prefetch next chunk while computing this one
            const float* h2 = hsrc + (c + 1) * 64;
            const float* u2 = usrc + (c + 1) * 64;
#pragma unroll
            for (int q = 0; q < 4; q++) hreg[q] = *(const float4*)(h2 + q * 4);
#pragma unroll
            for (int q = 0; q < 2; q++) ureg[q] = *(const float4*)(u2 + q * 4);
        }
#pragma unroll
        for (int kk = 0; kk < 64; ++kk) {
            float4 a = *(const float4*)&hs[kk][ty * 4];
            float2 u = *(const float2*)&us[kk][tx * 2];
            acc[0][0] += a.x * u.x; acc[0][1] += a.x * u.y;
            acc[1][0] += a.y * u.x; acc[1][1] += a.y * u.y;
            acc[2][0] += a.z * u.x; acc[2][1] += a.z * u.y;
            acc[3][0] += a.w * u.x; acc[3][1] += a.w * u.y;
        }
    }

    // z = acc + xW[t]; exchange through smem so gate quads line up per j
#pragma unroll
    for (int i = 0; i < 4; i++) {
        const int b = ty * 4 + i;
        const float* xrow = xw + (size_t)(b * TT + t) * G4H;
#pragma unroll
        for (int j = 0; j < 2; j++) {
            const int lc = tx * 2 + j;
            const int gcol = ((lc >> 3) * HH) + j0 + (lc & 7);
            zbuf[b][lc] = acc[i][j] + xrow[gcol];
        }
    }
    __syncthreads();

    // fused gate + cell update (512 hidden elems, 2 per thread)
#pragma unroll
    for (int q = 0; q < 2; q++) {
        const int e  = tid + q * 256;
        const int b  = e >> 3;
        const int jj = e & 7;
        const float ig = sigm(zbuf[b][jj]);
        const float fg = sigm(zbuf[b][8 + jj]);
        const float gg = sigm(zbuf[b][16 + jj]);
        const float og = sigm(zbuf[b][24 + jj]);
        const int hidx = b * HH + j0 + jj;
        const float cn = fg * cst[hidx] + ig * gg;
        const float hn = og * sigm(cn);
        cst[hidx]   = cn;
        hnext[hidx] = hn;
        dout[(size_t)b * (TT * HH) + t * HH + j0 + jj] += 0.5f * hn;
    }
}

// ---------------- final states: hF, cF, hB, cB ---------------------------
__global__ void finalize_kernel(float* __restrict__ dout) {
    int i = blockIdx.x * blockDim.x + threadIdx.x;
    if (i >= BB * HH) return;
    const int b = i >> 9, j = i & 511;
    dout[OUT0 + i]              = g_h[0][0][b][j];   // hF (512 steps -> pp 0)
    dout[OUT0 + 32768 + i]      = g_c[0][b][j];      // cF
    dout[OUT0 + 65536 + i]      = g_h[1][0][b][j];   // hB
    dout[OUT0 + 98304 + i]      = g_c[1][b][j];      // cB
}

// ---------------- launch ---------------------------------------------------
extern "C" void kernel_launch(void* const* d_in, const int* in_sizes, int n_in,
                              void* d_out, int out_size) {
    const float* x  = (const float*)d_in[0];
    // d_in[1] = hidden : unused by the reference (zero initial state)
    const float* Wf = (const float*)d_in[2];
    const float* Uf = (const float*)d_in[3];
    const float* bf = (const float*)d_in[4];
    const float* Wb = (const float*)d_in[5];
    const float* Ub = (const float*)d_in[6];
    const float* bb = (const float*)d_in[7];
    float* out = (float*)d_out;

    // zero the accumulated output region (both directions += into it)
    cudaMemsetAsync(d_out, 0, (size_t)OUT0 * sizeof(float), 0);

    // re-zero recurrent state every launch (graph replays reuse globals)
    init_state_kernel<<<512, 256>>>();

    // U transpose (Ut[col][k]) for contiguous per-column streaming
    transu_kernel<<<dim3(G4H / 32, HH / 32, 2), dim3(32, 32)>>>(Uf, Ub);

    // input projection for both directions
    proj_kernel<<<dim3(MROWS / 128, G4H / 128, 2), 256>>>(x, Wf, bf, Wb, bb);

    // sequential recurrence: one launch per step, fwd+bwd concurrent
    for (int s = 0; s < TT; ++s)
        step_kernel<<<dim3(HH / 8, 2), 256>>>(s, out);

    finalize_kernel<<<(BB * HH + 255) / 256, 256>>>(out);
}

// round 5
// speedup vs baseline: 1.3161x; 1.3161x over previous
#include <cuda_runtime.h>
#include <cstdint>

// Shapes (fixed)
#define BB 64
#define TT 512
#define DD 256
#define HH 512
#define G4H 2048           // 4*H
#define MROWS 32768        // B*T
#define OUT0 16777216      // B*T*H
#define NCTA 128           // persistent grid: 64 col-tiles x 2 dirs

// ---------------- device scratch ------------------------------------------
__device__ float g_xw[2][MROWS][G4H];   // x@W+b, row r = b*T + t
__device__ float g_h[2][2][BB][HH];     // [dir][pingpong][b][h]
__device__ float g_c[2][BB][HH];        // [dir][b][h]
__device__ unsigned g_bar_count;
__device__ unsigned g_bar_epoch;

__device__ __forceinline__ float sigm(float x) {
    return 1.0f / (1.0f + __expf(-x));
}

// ---------------- state init (replay-safe) --------------------------------
__global__ void init_state_kernel() {
    int i = blockIdx.x * blockDim.x + threadIdx.x;
    float* h = &g_h[0][0][0][0];
    float* c = &g_c[0][0][0];
    if (i < 2 * 2 * BB * HH) h[i] = 0.0f;
    if (i < 2 * BB * HH)     c[i] = 0.0f;
    if (i == 0) { g_bar_count = 0u; g_bar_epoch = 0u; }
}

// ---------------- input projection: g_xw = x @ W + b ----------------------
__global__ __launch_bounds__(256, 2) void proj_kernel(
    const float* __restrict__ x,
    const float* __restrict__ Wf, const float* __restrict__ bf,
    const float* __restrict__ Wb, const float* __restrict__ bb) {
    __shared__ float As[2][8][132];
    __shared__ float Bs[2][8][128];

    const int mt = blockIdx.x, nt = blockIdx.y, dir = blockIdx.z;
    const float* W    = dir ? Wb : Wf;
    const float* bias = dir ? bb : bf;
    float* xwout = &g_xw[dir][0][0];

    const int tid = threadIdx.x;
    const int ty = tid >> 4;
    const int tx = tid & 15;

    const int arow = tid >> 1, ak = (tid & 1) * 4;
    const int brow = tid >> 5, bcol = (tid & 31) * 4;
    const float* aptr = x + (size_t)(mt * 128 + arow) * DD + ak;
    const float* bptr = W + (size_t)brow * G4H + nt * 128 + bcol;

    float acc[8][8];
#pragma unroll
    for (int i = 0; i < 8; i++)
#pragma unroll
        for (int j = 0; j < 8; j++) acc[i][j] = 0.0f;

    float4 areg = *(const float4*)(aptr);
    float4 breg = *(const float4*)(bptr);

    for (int c = 0; c < 32; ++c) {
        const int buf = c & 1;
        As[buf][ak + 0][arow] = areg.x;
        As[buf][ak + 1][arow] = areg.y;
        As[buf][ak + 2][arow] = areg.z;
        As[buf][ak + 3][arow] = areg.w;
        *(float4*)&Bs[buf][brow][bcol] = breg;
        __syncthreads();
        if (c < 31) {
            areg = *(const float4*)(aptr + (c + 1) * 8);
            breg = *(const float4*)(bptr + (size_t)(c + 1) * 8 * G4H);
        }
#pragma unroll
        for (int kk = 0; kk < 8; ++kk) {
            float4 a0 = *(const float4*)&As[buf][kk][ty * 8];
            float4 a1 = *(const float4*)&As[buf][kk][ty * 8 + 4];
            float4 b0 = *(const float4*)&Bs[buf][kk][tx * 8];
            float4 b1 = *(const float4*)&Bs[buf][kk][tx * 8 + 4];
            float av[8] = {a0.x, a0.y, a0.z, a0.w, a1.x, a1.y, a1.z, a1.w};
            float bv[8] = {b0.x, b0.y, b0.z, b0.w, b1.x, b1.y, b1.z, b1.w};
#pragma unroll
            for (int i = 0; i < 8; i++)
#pragma unroll
                for (int j = 0; j < 8; j++) acc[i][j] += av[i] * bv[j];
        }
        __syncthreads();
    }

    float bv0[8];
#pragma unroll
    for (int j = 0; j < 8; j++) bv0[j] = bias[nt * 128 + tx * 8 + j];
#pragma unroll
    for (int i = 0; i < 8; i++) {
        const size_t row = (size_t)(mt * 128 + ty * 8 + i);
        float* dst = xwout + row * G4H + nt * 128 + tx * 8;
        float4 o0 = make_float4(acc[i][0] + bv0[0], acc[i][1] + bv0[1],
                                acc[i][2] + bv0[2], acc[i][3] + bv0[3]);
        float4 o1 = make_float4(acc[i][4] + bv0[4], acc[i][5] + bv0[5],
                                acc[i][6] + bv0[6], acc[i][7] + bv0[7]);
        *(float4*)(dst)     = o0;
        *(float4*)(dst + 4) = o1;
    }
}

// ---------------- persistent recurrence -----------------------------------
// Grid (64, 2): CTA = (col-tile jt, dir). Owns 8 hidden units (32 gate cols).
// U slice resident in SMEM for all 512 steps. Grid barrier between steps.
// SMEM: us[512][32] + hs[64][68] + zb[64][36] = 92160 B -> 1 CTA/SM.
__global__ __launch_bounds__(256, 1) void lstm_persistent(
    const float* __restrict__ Uf, const float* __restrict__ Ub,
    float* __restrict__ dout) {
    extern __shared__ float sm[];
    float* us = sm;                   // [512][32]
    float* hs = sm + 512 * 32;        // [64][68]  (k-major, padded)
    float* zb = hs + 64 * 68;         // [64][36]

    const int dir = blockIdx.y;
    const int jt  = blockIdx.x;
    const int j0  = jt * 8;
    const int tid = threadIdx.x;

    // ---- load resident U slice: us[k][lc], lc = gate*8 + jj -> col gate*512+j0+jj
    const float* U = dir ? Ub : Uf;
    for (int i = tid; i < 512 * 32; i += 256) {
        int k = i >> 5, lc = i & 31;
        int gcol = ((lc >> 3) << 9) + j0 + (lc & 7);
        us[i] = U[(size_t)k * G4H + gcol];
    }

    // GEMM thread roles: 2 k-slices x 128 threads, microtile 4b x 4c
    const int ks = tid >> 7;           // k-slice 0/1
    const int ti = tid & 127;
    const int bg = ti & 15;            // batch group (4 rows)
    const int cg = ti >> 4;            // col group (4 cols)
    // h loader role
    const int hb  = tid >> 2;          // 0..63
    const int hk0 = (tid & 3) * 16;
    // epilogue role (2 hidden elems per thread)
    const int b0 = tid >> 3,         jj0 = tid & 7;
    const int b1 = (tid >> 3) + 32,  jj1 = tid & 7;

    float* h0  = &g_h[dir][0][0][0];
    float* h1  = &g_h[dir][1][0][0];
    float* cst = &g_c[dir][0][0];
    const float* xw = &g_xw[dir][0][0];

    __syncthreads();  // us ready

    for (int s = 0; s < TT; ++s) {
        // ---- grid barrier: wait for previous step's h to be published
        if (tid == 0) {
            while (*((volatile unsigned*)&g_bar_epoch) < (unsigned)s) { }
        }
        __syncthreads();

        const int pr = s & 1;
        const float* hprev = pr ? h1 : h0;
        float*       hnext = pr ? h0 : h1;
        const int t = dir ? (TT - 1 - s) : s;

        // ---- prefetch xw gates, c-state, old dout (hidden behind GEMM)
        const float* xrow0 = xw + (size_t)(b0 * TT + t) * G4H + j0 + jj0;
        const float* xrow1 = xw + (size_t)(b1 * TT + t) * G4H + j0 + jj1;
        float xr0i = xrow0[0], xr0f = xrow0[512], xr0g = xrow0[1024], xr0o = xrow0[1536];
        float xr1i = xrow1[0], xr1f = xrow1[512], xr1g = xrow1[1024], xr1o = xrow1[1536];
        const size_t oidx0 = (size_t)b0 * (TT * HH) + (size_t)t * HH + j0 + jj0;
        const size_t oidx1 = (size_t)b1 * (TT * HH) + (size_t)t * HH + j0 + jj1;
        float dpre0 = 0.0f, dpre1 = 0.0f;
        if (s >= 256) { dpre0 = dout[oidx0]; dpre1 = dout[oidx1]; }
        const float cpre0 = cst[b0 * HH + j0 + jj0];
        const float cpre1 = cst[b1 * HH + j0 + jj1];

        // ---- GEMM: acc[4][4] += h[64xK] @ Uslice[Kx32], K split over 2 slices
        const float* hsrc = hprev + hb * HH + hk0;
        float4 hreg[4];
#pragma unroll
        for (int q = 0; q < 4; q++) hreg[q] = *(const float4*)(hsrc + q * 4);

        float acc[4][4];
#pragma unroll
        for (int i = 0; i < 4; i++)
#pragma unroll
            for (int j = 0; j < 4; j++) acc[i][j] = 0.0f;

        for (int c = 0; c < 8; ++c) {
            __syncthreads();  // previous chunk compute done
#pragma unroll
            for (int q = 0; q < 4; q++) {
                hs[(hk0 + q * 4 + 0) * 68 + hb] = hreg[q].x;
                hs[(hk0 + q * 4 + 1) * 68 + hb] = hreg[q].y;
                hs[(hk0 + q * 4 + 2) * 68 + hb] = hreg[q].z;
                hs[(hk0 + q * 4 + 3) * 68 + hb] = hreg[q].w;
            }
            __syncthreads();
            if (c < 7) {
                const float* h2 = hsrc + (c + 1) * 64;
#pragma unroll
                for (int q = 0; q < 4; q++) hreg[q] = *(const float4*)(h2 + q * 4);
            }
            const float* urow = us + (c * 64 + ks * 32) * 32 + cg * 4;
            const float* hrow = hs + (ks * 32) * 68 + bg * 4;
#pragma unroll 8
            for (int kk = 0; kk < 32; ++kk) {
                float4 a = *(const float4*)(hrow + kk * 68);
                float4 u = *(const float4*)(urow + kk * 32);
                acc[0][0] += a.x * u.x; acc[0][1] += a.x * u.y;
                acc[0][2] += a.x * u.z; acc[0][3] += a.x * u.w;
                acc[1][0] += a.y * u.x; acc[1][1] += a.y * u.y;
                acc[1][2] += a.y * u.z; acc[1][3] += a.y * u.w;
                acc[2][0] += a.z * u.x; acc[2][1] += a.z * u.y;
                acc[2][2] += a.z * u.z; acc[2][3] += a.z * u.w;
                acc[3][0] += a.w * u.x; acc[3][1] += a.w * u.y;
                acc[3][2] += a.w * u.z; acc[3][3] += a.w * u.w;
            }
        }

        // ---- reduce the two k-slices into zb[b][lc]
        __syncthreads();
        if (ks == 0) {
#pragma unroll
            for (int i = 0; i < 4; i++)
#pragma unroll
                for (int j = 0; j < 4; j++)
                    zb[(bg * 4 + i) * 36 + cg * 4 + j] = acc[i][j];
        }
        __syncthreads();
        if (ks == 1) {
#pragma unroll
            for (int i = 0; i < 4; i++)
#pragma unroll
                for (int j = 0; j < 4; j++)
                    zb[(bg * 4 + i) * 36 + cg * 4 + j] += acc[i][j];
        }
        __syncthreads();

        // ---- fused gates + cell update + output
        {
            const float ig = sigm(zb[b0 * 36 + jj0]       + xr0i);
            const float fg = sigm(zb[b0 * 36 + 8  + jj0]  + xr0f);
            const float gg = sigm(zb[b0 * 36 + 16 + jj0]  + xr0g);
            const float og = sigm(zb[b0 * 36 + 24 + jj0]  + xr0o);
            const float cn = fg * cpre0 + ig * gg;
            const float hn = og * sigm(cn);
            cst[b0 * HH + j0 + jj0]   = cn;
            hnext[b0 * HH + j0 + jj0] = hn;
            dout[oidx0] = 0.5f * hn + dpre0;   // s<256: dpre=0 plain store
        }
        {
            const float ig = sigm(zb[b1 * 36 + jj1]       + xr1i);
            const float fg = sigm(zb[b1 * 36 + 8  + jj1]  + xr1f);
            const float gg = sigm(zb[b1 * 36 + 16 + jj1]  + xr1g);
            const float og = sigm(zb[b1 * 36 + 24 + jj1]  + xr1o);
            const float cn = fg * cpre1 + ig * gg;
            const float hn = og * sigm(cn);
            cst[b1 * HH + j0 + jj1]   = cn;
            hnext[b1 * HH + j0 + jj1] = hn;
            dout[oidx1] = 0.5f * hn + dpre1;
        }

        // ---- publish + arrive
        __threadfence();
        __syncthreads();
        if (tid == 0) {
            unsigned v = atomicAdd(&g_bar_count, 1u);
            if (v == NCTA - 1) {
                atomicExch(&g_bar_count, 0u);
                __threadfence();
                atomicAdd(&g_bar_epoch, 1u);
            }
        }
    }
}

// ---------------- final states: hF, cF, hB, cB ----------------------------
__global__ void finalize_kernel(float* __restrict__ dout) {
    int i = blockIdx.x * blockDim.x + threadIdx.x;
    if (i >= BB * HH) return;
    const int b = i >> 9, j = i & 511;
    dout[OUT0 + i]         = g_h[0][0][b][j];   // hF (512 steps -> pingpong 0)
    dout[OUT0 + 32768 + i] = g_c[0][b][j];      // cF
    dout[OUT0 + 65536 + i] = g_h[1][0][b][j];   // hB
    dout[OUT0 + 98304 + i] = g_c[1][b][j];      // cB
}

// ---------------- launch ---------------------------------------------------
extern "C" void kernel_launch(void* const* d_in, const int* in_sizes, int n_in,
                              void* d_out, int out_size) {
    const float* x  = (const float*)d_in[0];
    // d_in[1] = hidden : unused by the reference (zero initial state)
    const float* Wf = (const float*)d_in[2];
    const float* Uf = (const float*)d_in[3];
    const float* bf = (const float*)d_in[4];
    const float* Wb = (const float*)d_in[5];
    const float* Ub = (const float*)d_in[6];
    const float* bb = (const float*)d_in[7];
    float* out = (float*)d_out;

    const int smem_bytes = (512 * 32 + 64 * 68 + 64 * 36) * sizeof(float); // 92160
    cudaFuncSetAttribute(lstm_persistent,
                         cudaFuncAttributeMaxDynamicSharedMemorySize, smem_bytes);

    // re-zero recurrent state + barrier every launch (graph replay safe)
    init_state_kernel<<<512, 256>>>();

    // input projection for both directions
    proj_kernel<<<dim3(MROWS / 128, G4H / 128, 2), 256>>>(x, Wf, bf, Wb, bb);

    // persistent recurrence: one kernel, 512 internal steps, grid barrier
    lstm_persistent<<<dim3(64, 2), 256, smem_bytes>>>(Uf, Ub, out);

    finalize_kernel<<<(BB * HH + 255) / 256, 256>>>(out);
}

// round 8
// speedup vs baseline: 1.3349x; 1.0143x over previous
#include <cuda_runtime.h>
#include <cstdint>

// Shapes (fixed)
#define BB 64
#define TT 512
#define DD 256
#define HH 512
#define G4H 2048           // 4*H
#define MROWS 32768        // B*T
#define OUT0 16777216      // B*T*H
#define NCTA 128           // persistent grid: 64 col-tiles x 2 dirs

// ---------------- device scratch ------------------------------------------
__device__ float g_xw[2][MROWS][G4H];      // x@W+b, row r = b*T + t
__device__ float g_hout[2][BB][TT][HH];    // per-direction hidden sequence
__device__ float g_h[2][2][BB][HH];        // [dir][pingpong][b][h]
__device__ float g_c[2][BB][HH];           // [dir][b][h]
__device__ unsigned g_bar_count;
__device__ unsigned g_bar_epoch;

__device__ __forceinline__ float sigm(float x) {
    return 1.0f / (1.0f + __expf(-x));
}

// packed f32x2 helpers (exact fp32 semantics, 2 FMAs / instruction)
__device__ __forceinline__ void fma2(unsigned long long& acc,
                                     unsigned long long a,
                                     unsigned long long b) {
    asm("fma.rn.f32x2 %0,%1,%2,%0;" : "+l"(acc) : "l"(a), "l"(b));
}
__device__ __forceinline__ unsigned long long dup2(float v) {
    unsigned long long r;
    asm("mov.b64 %0,{%1,%1};" : "=l"(r) : "f"(v));
    return r;
}
__device__ __forceinline__ void unpack2(unsigned long long p, float& lo, float& hi) {
    asm("mov.b64 {%0,%1},%2;" : "=f"(lo), "=f"(hi) : "l"(p));
}

// ---------------- state init (replay-safe) --------------------------------
__global__ void init_state_kernel() {
    int i = blockIdx.x * blockDim.x + threadIdx.x;
    float* h = &g_h[0][0][0][0];
    float* c = &g_c[0][0][0];
    if (i < 2 * 2 * BB * HH) h[i] = 0.0f;
    if (i < 2 * BB * HH)     c[i] = 0.0f;
    if (i == 0) { g_bar_count = 0u; g_bar_epoch = 0u; }
}

// ---------------- input projection: g_xw = x @ W + b ----------------------
// 128x128 tile, 8x8 microtile via f32x2 (row pairs packed), 256 threads.
__global__ __launch_bounds__(256, 2) void proj_kernel(
    const float* __restrict__ x,
    const float* __restrict__ Wf, const float* __restrict__ bf,
    const float* __restrict__ Wb, const float* __restrict__ bb) {
    __shared__ float As[2][8][132];
    __shared__ float Bs[2][8][128];

    const int mt = blockIdx.x, nt = blockIdx.y, dir = blockIdx.z;
    const float* W    = dir ? Wb : Wf;
    const float* bias = dir ? bb : bf;
    float* xwout = &g_xw[dir][0][0];

    const int tid = threadIdx.x;
    const int ty = tid >> 4;
    const int tx = tid & 15;

    const int arow = tid >> 1, ak = (tid & 1) * 4;
    const int brow = tid >> 5, bcol = (tid & 31) * 4;
    const float* aptr = x + (size_t)(mt * 128 + arow) * DD + ak;
    const float* bptr = W + (size_t)brow * G4H + nt * 128 + bcol;

    unsigned long long accp[4][8];   // row-pair rp x col j
#pragma unroll
    for (int rp = 0; rp < 4; rp++)
#pragma unroll
        for (int j = 0; j < 8; j++) accp[rp][j] = 0ULL;

    float4 areg = *(const float4*)(aptr);
    float4 breg = *(const float4*)(bptr);

    for (int c = 0; c < 32; ++c) {
        const int buf = c & 1;
        As[buf][ak + 0][arow] = areg.x;
        As[buf][ak + 1][arow] = areg.y;
        As[buf][ak + 2][arow] = areg.z;
        As[buf][ak + 3][arow] = areg.w;
        *(float4*)&Bs[buf][brow][bcol] = breg;
        __syncthreads();
        if (c < 31) {
            areg = *(const float4*)(aptr + (c + 1) * 8);
            breg = *(const float4*)(bptr + (size_t)(c + 1) * 8 * G4H);
        }
#pragma unroll
        for (int kk = 0; kk < 8; ++kk) {
            ulonglong2 a01 = *(const ulonglong2*)&As[buf][kk][ty * 8];     // rows 0-3
            ulonglong2 a23 = *(const ulonglong2*)&As[buf][kk][ty * 8 + 4]; // rows 4-7
            float4 b0 = *(const float4*)&Bs[buf][kk][tx * 8];
            float4 b1 = *(const float4*)&Bs[buf][kk][tx * 8 + 4];
            unsigned long long bd[8];
            bd[0] = dup2(b0.x); bd[1] = dup2(b0.y); bd[2] = dup2(b0.z); bd[3] = dup2(b0.w);
            bd[4] = dup2(b1.x); bd[5] = dup2(b1.y); bd[6] = dup2(b1.z); bd[7] = dup2(b1.w);
#pragma unroll
            for (int j = 0; j < 8; j++) {
                fma2(accp[0][j], a01.x, bd[j]);
                fma2(accp[1][j], a01.y, bd[j]);
                fma2(accp[2][j], a23.x, bd[j]);
                fma2(accp[3][j], a23.y, bd[j]);
            }
        }
        __syncthreads();
    }

    float acc[8][8];
#pragma unroll
    for (int rp = 0; rp < 4; rp++)
#pragma unroll
        for (int j = 0; j < 8; j++)
            unpack2(accp[rp][j], acc[2 * rp][j], acc[2 * rp + 1][j]);

    float bv0[8];
#pragma unroll
    for (int j = 0; j < 8; j++) bv0[j] = bias[nt * 128 + tx * 8 + j];
#pragma unroll
    for (int i = 0; i < 8; i++) {
        const size_t row = (size_t)(mt * 128 + ty * 8 + i);
        float* dst = xwout + row * G4H + nt * 128 + tx * 8;
        float4 o0 = make_float4(acc[i][0] + bv0[0], acc[i][1] + bv0[1],
                                acc[i][2] + bv0[2], acc[i][3] + bv0[3]);
        float4 o1 = make_float4(acc[i][4] + bv0[4], acc[i][5] + bv0[5],
                                acc[i][6] + bv0[6], acc[i][7] + bv0[7]);
        *(float4*)(dst)     = o0;
        *(float4*)(dst + 4) = o1;
    }
}

// ---------------- persistent recurrence -----------------------------------
// Grid (64, 2): CTA = (col-tile jt, dir). 8 hidden units (32 gate cols).
// U slice resident in SMEM. R5-proven global grid barrier between steps.
// SMEM: us[512][32] + hs[64][68] + zb[2][64][36] = 101376 B -> 1 CTA/SM.
__global__ __launch_bounds__(256, 1) void lstm_persistent(
    const float* __restrict__ Uf, const float* __restrict__ Ub) {
    extern __shared__ float sm[];
    float* us  = sm;                   // [512][32]
    float* hs  = sm + 512 * 32;        // [64][68]  (k-major, padded)
    float* zb0 = hs + 64 * 68;         // [64][36]  k-slice 0
    float* zb1 = zb0 + 64 * 36;        // [64][36]  k-slice 1

    const int dir = blockIdx.y;
    const int jt  = blockIdx.x;
    const int j0  = jt * 8;
    const int tid = threadIdx.x;

    // resident U slice: us[k][lc], lc = gate*8 + jj -> col gate*512 + j0 + jj
    const float* U = dir ? Ub : Uf;
    for (int i = tid; i < 512 * 32; i += 256) {
        int k = i >> 5, lc = i & 31;
        int gcol = ((lc >> 3) << 9) + j0 + (lc & 7);
        us[i] = U[(size_t)k * G4H + gcol];
    }

    // GEMM roles: 2 k-slices x 128 threads, microtile 4b x 4c (f32x2 pairs)
    const int ks = tid >> 7;
    const int ti = tid & 127;
    const int bg = ti & 15;            // batch group (4 rows)
    const int cg = ti >> 4;            // col group (4 cols)
    // h loader role
    const int hb  = tid >> 2;          // 0..63
    const int hk0 = (tid & 3) * 16;
    // epilogue role (2 hidden elems per thread)
    const int b0 = tid >> 3,        jj0 = tid & 7;
    const int b1 = (tid >> 3) + 32, jj1 = tid & 7;

    float* h0  = &g_h[dir][0][0][0];
    float* h1  = &g_h[dir][1][0][0];
    float* cst = &g_c[dir][0][0];
    const float* xw = &g_xw[dir][0][0];
    float* hout = &g_hout[dir][0][0][0];

    float* zbme = ks ? zb1 : zb0;

    __syncthreads();  // us ready

    for (int s = 0; s < TT; ++s) {
        // ---- global grid barrier (exact R5 pattern, proven)
        if (tid == 0) {
            while (*((volatile unsigned*)&g_bar_epoch) < (unsigned)s) { }
        }
        __syncthreads();

        const int pr = s & 1;
        const float* hprev = pr ? h1 : h0;
        float*       hnext = pr ? h0 : h1;
        const int t = dir ? (TT - 1 - s) : s;

        // ---- prefetch xw gates + c-state (consumed at epilogue)
        const float* xrow0 = xw + (size_t)(b0 * TT + t) * G4H + j0 + jj0;
        const float* xrow1 = xw + (size_t)(b1 * TT + t) * G4H + j0 + jj1;
        float xr0i = xrow0[0], xr0f = xrow0[512], xr0g = xrow0[1024], xr0o = xrow0[1536];
        float xr1i = xrow1[0], xr1f = xrow1[512], xr1g = xrow1[1024], xr1o = xrow1[1536];
        const float cpre0 = cst[b0 * HH + j0 + jj0];
        const float cpre1 = cst[b1 * HH + j0 + jj1];

        // ---- GEMM: z[64x32] = h[64x512] @ Uslice, K split over 2 slices
        const float* hsrc = hprev + hb * HH + hk0;
        float4 hreg[4];
#pragma unroll
        for (int q = 0; q < 4; q++) hreg[q] = *(const float4*)(hsrc + q * 4);

        unsigned long long accp[2][4];   // row-pair rp x col j
#pragma unroll
        for (int rp = 0; rp < 2; rp++)
#pragma unroll
            for (int j = 0; j < 4; j++) accp[rp][j] = 0ULL;

        for (int c = 0; c < 8; ++c) {
            __syncthreads();
#pragma unroll
            for (int q = 0; q < 4; q++) {
                hs[(hk0 + q * 4 + 0) * 68 + hb] = hreg[q].x;
                hs[(hk0 + q * 4 + 1) * 68 + hb] = hreg[q].y;
                hs[(hk0 + q * 4 + 2) * 68 + hb] = hreg[q].z;
                hs[(hk0 + q * 4 + 3) * 68 + hb] = hreg[q].w;
            }
            __syncthreads();
            if (c < 7) {
                const float* h2 = hsrc + (c + 1) * 64;
#pragma unroll
                for (int q = 0; q < 4; q++) hreg[q] = *(const float4*)(h2 + q * 4);
            }
            const float* urow = us + (c * 64 + ks * 32) * 32 + cg * 4;
            const float* hrow = hs + (ks * 32) * 68 + bg * 4;
#pragma unroll 8
            for (int kk = 0; kk < 32; ++kk) {
                ulonglong2 ap = *(const ulonglong2*)(hrow + kk * 68);
                float4 u = *(const float4*)(urow + kk * 32);
                unsigned long long ud0 = dup2(u.x), ud1 = dup2(u.y);
                unsigned long long ud2 = dup2(u.z), ud3 = dup2(u.w);
                fma2(accp[0][0], ap.x, ud0); fma2(accp[0][1], ap.x, ud1);
                fma2(accp[0][2], ap.x, ud2); fma2(accp[0][3], ap.x, ud3);
                fma2(accp[1][0], ap.y, ud0); fma2(accp[1][1], ap.y, ud1);
                fma2(accp[1][2], ap.y, ud2); fma2(accp[1][3], ap.y, ud3);
            }
        }

        // ---- spill per-slice partials into separate banks (no inter-dep)
#pragma unroll
        for (int rp = 0; rp < 2; rp++)
#pragma unroll
            for (int j = 0; j < 4; j++) {
                float lo, hi;
                unpack2(accp[rp][j], lo, hi);
                zbme[(bg * 4 + 2 * rp + 0) * 36 + cg * 4 + j] = lo;
                zbme[(bg * 4 + 2 * rp + 1) * 36 + cg * 4 + j] = hi;
            }
        __syncthreads();

        // ---- fused gates + cell update + output (per-direction buffer)
        {
            const float ig = sigm(zb0[b0 * 36 + jj0]      + zb1[b0 * 36 + jj0]      + xr0i);
            const float fg = sigm(zb0[b0 * 36 + 8 + jj0]  + zb1[b0 * 36 + 8 + jj0]  + xr0f);
            const float gg = sigm(zb0[b0 * 36 + 16 + jj0] + zb1[b0 * 36 + 16 + jj0] + xr0g);
            const float og = sigm(zb0[b0 * 36 + 24 + jj0] + zb1[b0 * 36 + 24 + jj0] + xr0o);
            const float cn = fg * cpre0 + ig * gg;
            const float hn = og * sigm(cn);
            cst[b0 * HH + j0 + jj0]   = cn;
            hnext[b0 * HH + j0 + jj0] = hn;
            hout[(size_t)b0 * (TT * HH) + (size_t)t * HH + j0 + jj0] = hn;
        }
        {
            const float ig = sigm(zb0[b1 * 36 + jj1]      + zb1[b1 * 36 + jj1]      + xr1i);
            const float fg = sigm(zb0[b1 * 36 + 8 + jj1]  + zb1[b1 * 36 + 8 + jj1]  + xr1f);
            const float gg = sigm(zb0[b1 * 36 + 16 + jj1] + zb1[b1 * 36 + 16 + jj1] + xr1g);
            const float og = sigm(zb0[b1 * 36 + 24 + jj1] + zb1[b1 * 36 + 24 + jj1] + xr1o);
            const float cn = fg * cpre1 + ig * gg;
            const float hn = og * sigm(cn);
            cst[b1 * HH + j0 + jj1]   = cn;
            hnext[b1 * HH + j0 + jj1] = hn;
            hout[(size_t)b1 * (TT * HH) + (size_t)t * HH + j0 + jj1] = hn;
        }

        // ---- publish + arrive (R5 pattern: count reset by last arriver)
        __threadfence();
        __syncthreads();
        if (tid == 0) {
            unsigned v = atomicAdd(&g_bar_count, 1u);
            if (v == NCTA - 1) {
                atomicExch(&g_bar_count, 0u);
                __threadfence();
                atomicAdd(&g_bar_epoch, 1u);
            }
        }
    }
}

// ---------------- combine: out = 0.5*(h_f + h_b) ---------------------------
__global__ void combine_kernel(float* __restrict__ dout) {
    const int i = blockIdx.x * 256 + threadIdx.x;   // OUT0/4 float4 elems
    const float4 a = ((const float4*)&g_hout[0][0][0][0])[i];
    const float4 b = ((const float4*)&g_hout[1][0][0][0])[i];
    ((float4*)dout)[i] = make_float4(0.5f * (a.x + b.x), 0.5f * (a.y + b.y),
                                     0.5f * (a.z + b.z), 0.5f * (a.w + b.w));
}

// ---------------- final states: hF, cF, hB, cB ----------------------------
__global__ void finalize_kernel(float* __restrict__ dout) {
    int i = blockIdx.x * blockDim.x + threadIdx.x;
    if (i >= BB * HH) return;
    const int b = i >> 9, j = i & 511;
    dout[OUT0 + i]         = g_h[0][0][b][j];   // hF (512 steps -> pingpong 0)
    dout[OUT0 + 32768 + i] = g_c[0][b][j];      // cF
    dout[OUT0 + 65536 + i] = g_h[1][0][b][j];   // hB
    dout[OUT0 + 98304 + i] = g_c[1][b][j];      // cB
}

// ---------------- launch ---------------------------------------------------
extern "C" void kernel_launch(void* const* d_in, const int* in_sizes, int n_in,
                              void* d_out, int out_size) {
    const float* x  = (const float*)d_in[0];
    // d_in[1] = hidden : unused by the reference (zero initial state)
    const float* Wf = (const float*)d_in[2];
    const float* Uf = (const float*)d_in[3];
    const float* bf = (const float*)d_in[4];
    const float* Wb = (const float*)d_in[5];
    const float* Ub = (const float*)d_in[6];
    const float* bb = (const float*)d_in[7];
    float* out = (float*)d_out;

    const int smem_bytes = (512 * 32 + 64 * 68 + 2 * 64 * 36) * sizeof(float); // 101376
    cudaFuncSetAttribute(lstm_persistent,
                         cudaFuncAttributeMaxDynamicSharedMemorySize, smem_bytes);

    // re-zero recurrent state + barrier every launch (graph replay safe)
    init_state_kernel<<<512, 256>>>();

    // input projection for both directions
    proj_kernel<<<dim3(MROWS / 128, G4H / 128, 2), 256>>>(x, Wf, bf, Wb, bb);

    // persistent recurrence: one kernel, 512 internal steps, grid barrier
    lstm_persistent<<<dim3(64, 2), 256, smem_bytes>>>(Uf, Ub);

    // blend directions + emit final states
    combine_kernel<<<OUT0 / 4 / 256, 256>>>(out);
    finalize_kernel<<<(BB * HH + 255) / 256, 256>>>(out);
}

// round 11
// speedup vs baseline: 1.9436x; 1.4560x over previous
#include <cuda_runtime.h>
#include <cuda_bf16.h>
#include <cstdint>

// Shapes (fixed)
#define BB 64
#define TT 512
#define DD 256
#define HH 512
#define G4H 2048           // 4*H
#define MROWS 32768        // B*T
#define OUT0 16777216      // B*T*H
#define NCTA 128           // persistent grid: 64 col-tiles x 2 dirs

// ---------------- device scratch ------------------------------------------
__device__ float g_xw[2][MROWS][G4H];               // x@W+b, row r = b*T + t
__device__ float g_hout[2][BB][TT][HH];             // per-direction hidden seq
__device__ __nv_bfloat16 g_hbf[2][2][2][BB][HH];    // [dir][pingpong][hi/lo][b][k]
__device__ unsigned g_bar_count;
__device__ unsigned g_bar_epoch;

__device__ __forceinline__ float sigm(float x) {
    return 1.0f / (1.0f + __expf(-x));
}

__device__ __forceinline__ uint32_t s2u(const void* p) {
    uint32_t a;
    asm("{ .reg .u64 t; cvta.to.shared.u64 t, %1; cvt.u32.u64 %0, t; }"
        : "=r"(a) : "l"(p));
    return a;
}

// ---- warp-level tensor ops (sm_80-baseline PTX; works on compute_103) ----
__device__ __forceinline__ void ldsm4(uint32_t& a0, uint32_t& a1,
                                      uint32_t& a2, uint32_t& a3, uint32_t addr) {
    asm volatile("ldmatrix.sync.aligned.m8n8.x4.shared.b16 {%0,%1,%2,%3}, [%4];"
                 : "=r"(a0), "=r"(a1), "=r"(a2), "=r"(a3) : "r"(addr));
}
__device__ __forceinline__ void ldsm2(uint32_t& b0, uint32_t& b1, uint32_t addr) {
    asm volatile("ldmatrix.sync.aligned.m8n8.x2.shared.b16 {%0,%1}, [%2];"
                 : "=r"(b0), "=r"(b1) : "r"(addr));
}
__device__ __forceinline__ void mma16816(float* d, const uint32_t* a,
                                         uint32_t b0, uint32_t b1) {
    asm volatile(
        "mma.sync.aligned.m16n8k16.row.col.f32.bf16.bf16.f32 "
        "{%0,%1,%2,%3}, {%4,%5,%6,%7}, {%8,%9}, {%0,%1,%2,%3};"
        : "+f"(d[0]), "+f"(d[1]), "+f"(d[2]), "+f"(d[3])
        : "r"(a[0]), "r"(a[1]), "r"(a[2]), "r"(a[3]), "r"(b0), "r"(b1));
}

// ---------------- state init (replay-safe) --------------------------------
__global__ void init_state_kernel() {
    int i = blockIdx.x * blockDim.x + threadIdx.x;   // 131072 threads
    ((uint32_t*)&g_hbf[0][0][0][0][0])[i] = 0u;      // 512KB of bf16 zeros
    if (i == 0) { g_bar_count = 0u; g_bar_epoch = 0u; }
}

// ---------------- input projection: g_xw = x @ W + b ----------------------
__global__ __launch_bounds__(256, 2) void proj_kernel(
    const float* __restrict__ x,
    const float* __restrict__ Wf, const float* __restrict__ bf,
    const float* __restrict__ Wb, const float* __restrict__ bb) {
    __shared__ float As[2][8][132];
    __shared__ float Bs[2][8][128];

    const int mt = blockIdx.x, nt = blockIdx.y, dir = blockIdx.z;
    const float* W    = dir ? Wb : Wf;
    const float* bias = dir ? bb : bf;
    float* xwout = &g_xw[dir][0][0];

    const int tid = threadIdx.x;
    const int ty = tid >> 4;
    const int tx = tid & 15;

    const int arow = tid >> 1, ak = (tid & 1) * 4;
    const int brow = tid >> 5, bcol = (tid & 31) * 4;
    const float* aptr = x + (size_t)(mt * 128 + arow) * DD + ak;
    const float* bptr = W + (size_t)brow * G4H + nt * 128 + bcol;

    float acc[8][8];
#pragma unroll
    for (int i = 0; i < 8; i++)
#pragma unroll
        for (int j = 0; j < 8; j++) acc[i][j] = 0.0f;

    float4 areg = *(const float4*)(aptr);
    float4 breg = *(const float4*)(bptr);

    for (int c = 0; c < 32; ++c) {
        const int buf = c & 1;
        As[buf][ak + 0][arow] = areg.x;
        As[buf][ak + 1][arow] = areg.y;
        As[buf][ak + 2][arow] = areg.z;
        As[buf][ak + 3][arow] = areg.w;
        *(float4*)&Bs[buf][brow][bcol] = breg;
        __syncthreads();
        if (c < 31) {
            areg = *(const float4*)(aptr + (c + 1) * 8);
            breg = *(const float4*)(bptr + (size_t)(c + 1) * 8 * G4H);
        }
#pragma unroll
        for (int kk = 0; kk < 8; ++kk) {
            float4 a0 = *(const float4*)&As[buf][kk][ty * 8];
            float4 a1 = *(const float4*)&As[buf][kk][ty * 8 + 4];
            float4 b0 = *(const float4*)&Bs[buf][kk][tx * 8];
            float4 b1 = *(const float4*)&Bs[buf][kk][tx * 8 + 4];
            float av[8] = {a0.x, a0.y, a0.z, a0.w, a1.x, a1.y, a1.z, a1.w};
            float bv[8] = {b0.x, b0.y, b0.z, b0.w, b1.x, b1.y, b1.z, b1.w};
#pragma unroll
            for (int i = 0; i < 8; i++)
#pragma unroll
                for (int j = 0; j < 8; j++) acc[i][j] += av[i] * bv[j];
        }
        __syncthreads();
    }

    float bv0[8];
#pragma unroll
    for (int j = 0; j < 8; j++) bv0[j] = bias[nt * 128 + tx * 8 + j];
#pragma unroll
    for (int i = 0; i < 8; i++) {
        const size_t row = (size_t)(mt * 128 + ty * 8 + i);
        float* dst = xwout + row * G4H + nt * 128 + tx * 8;
        float4 o0 = make_float4(acc[i][0] + bv0[0], acc[i][1] + bv0[1],
                                acc[i][2] + bv0[2], acc[i][3] + bv0[3]);
        float4 o1 = make_float4(acc[i][4] + bv0[4], acc[i][5] + bv0[5],
                                acc[i][6] + bv0[6], acc[i][7] + bv0[7]);
        *(float4*)(dst)     = o0;
        *(float4*)(dst + 4) = o1;
    }
}

// ---------------- persistent tensor recurrence ----------------------------
// Grid (64, 2): CTA = (col-tile jt, dir), owns 8 hidden units (32 gate cols).
// z[64x32] = h[64x512] @ U-slice via mma.sync bf16 hi/lo split (3 terms).
// h stored in global as bf16 hi/lo by the epilogue; U resident in SMEM.
//
// SMEM layout (bytes), stride 520 halfs (=65 x 16B banks: ldmatrix clean):
#define HSTR 520
#define HS_HI 0
#define HS_LO 66560
#define US_HI 133120
#define US_LO 166400
#define ZB    199680         // float zb[64][34]
#define SMEM_TOTAL 208384

__global__ __launch_bounds__(256, 1) void lstm_persistent(
    const float* __restrict__ Uf, const float* __restrict__ Ub,
    float* __restrict__ dout) {
    extern __shared__ char smc[];
    const uint32_t smb = s2u(smc);
    float* zb = (float*)(smc + ZB);

    const int dir = blockIdx.y;
    const int jt  = blockIdx.x;
    const int j0  = jt * 8;
    const int tid = threadIdx.x;
    const int w   = tid >> 5;
    const int lane = tid & 31;

    // ---- resident U slice as bf16 hi/lo, [n=32][k=512] row-major ----
    const float* U = dir ? Ub : Uf;
    for (int i = tid; i < 32 * 512; i += 256) {
        const int n = i >> 9, k = i & 511;
        const int gcol = ((n >> 3) << 9) + j0 + (n & 7);
        const float v = U[(size_t)k * G4H + gcol];
        const __nv_bfloat16 hi = __float2bfloat16_rn(v);
        const __nv_bfloat16 lo = __float2bfloat16_rn(v - __bfloat162float(hi));
        *(__nv_bfloat16*)(smc + US_HI + (n * HSTR + k) * 2) = hi;
        *(__nv_bfloat16*)(smc + US_LO + (n * HSTR + k) * 2) = lo;
    }

    // ---- MMA roles: warp w -> rows mb*16..+15, cols (w&1)*16..+15 ----
    const int mb  = w >> 1;
    const int nb0 = (w & 1) * 2;   // two n-blocks of 8
    const uint32_t aoff = (uint32_t)(((mb * 16 + (lane & 15)) * HSTR +
                                      ((lane >> 4) & 1) * 8) * 2);
    const uint32_t aHi = smb + HS_HI + aoff;
    const uint32_t aLo = smb + HS_LO + aoff;
    const uint32_t boff = (uint32_t)(((nb0 * 8 + (lane & 7)) * HSTR +
                                      (lane & 8)) * 2);
    const uint32_t b0Hi = smb + US_HI + boff;
    const uint32_t b1Hi = b0Hi + 8 * HSTR * 2;
    const uint32_t b0Lo = smb + US_LO + boff;
    const uint32_t b1Lo = b0Lo + 8 * HSTR * 2;

    const float* xw = &g_xw[dir][0][0];
    float* hout = &g_hout[dir][0][0][0];

    float creg[8];
#pragma unroll
    for (int j = 0; j < 8; j++) creg[j] = 0.0f;

    __syncthreads();  // U ready

    for (int s = 0; s < TT; ++s) {
        // ---- grid barrier (proven pattern) ----
        if (tid == 0) {
            while (*((volatile unsigned*)&g_bar_epoch) < (unsigned)s) { }
        }
        __syncthreads();

        const int pr = s & 1;
        const int t = dir ? (TT - 1 - s) : s;

        // ---- epilogue operand prefetch (warps 0,1: thread = batch row) ----
        float xg[4][8];
        if (tid < 64) {
            const float* xrow = xw + (size_t)(tid * TT + t) * G4H + j0;
#pragma unroll
            for (int g = 0; g < 4; g++) {
                float4 a = *(const float4*)(xrow + g * 512);
                float4 b = *(const float4*)(xrow + g * 512 + 4);
                xg[g][0] = a.x; xg[g][1] = a.y; xg[g][2] = a.z; xg[g][3] = a.w;
                xg[g][4] = b.x; xg[g][5] = b.y; xg[g][6] = b.z; xg[g][7] = b.w;
            }
        }

        // ---- copy h (bf16 hi/lo) global -> smem: 8192 uint4 ----
        {
            const uint4* src = (const uint4*)&g_hbf[dir][pr][0][0][0];
#pragma unroll
            for (int q = 0; q < 32; ++q) {
                const int i = tid + q * 256;          // 0..8191
                const int m = i >> 12;                // 0: hi, 1: lo
                const int r = (i >> 6) & 63;
                const int c16 = i & 63;
                uint4 v = src[i];
                *(uint4*)(smc + (m ? HS_LO : HS_HI) + (r * HSTR + c16 * 8) * 2) = v;
            }
        }
        __syncthreads();

        // ---- tensor GEMM: 3 terms, K=512 in 32 chunks of 16 ----
        float d0[4] = {0.f, 0.f, 0.f, 0.f};
        float d1[4] = {0.f, 0.f, 0.f, 0.f};
#pragma unroll 4
        for (int k0 = 0; k0 < 512; k0 += 16) {
            const uint32_t ko = (uint32_t)(k0 * 2);
            uint32_t ah[4], al[4], bh0[2], bh1[2], bl0[2], bl1[2];
            ldsm4(ah[0], ah[1], ah[2], ah[3], aHi + ko);
            ldsm2(bh0[0], bh0[1], b0Hi + ko);
            ldsm2(bh1[0], bh1[1], b1Hi + ko);
            ldsm2(bl0[0], bl0[1], b0Lo + ko);
            ldsm2(bl1[0], bl1[1], b1Lo + ko);
            ldsm4(al[0], al[1], al[2], al[3], aLo + ko);
            mma16816(d0, ah, bh0[0], bh0[1]);
            mma16816(d1, ah, bh1[0], bh1[1]);
            mma16816(d0, ah, bl0[0], bl0[1]);
            mma16816(d1, ah, bl1[0], bl1[1]);
            mma16816(d0, al, bh0[0], bh0[1]);
            mma16816(d1, al, bh1[0], bh1[1]);
        }

        // ---- exchange accumulators through zb[64][34] ----
        {
            const int r0 = mb * 16 + (lane >> 2);
            const int c0 = nb0 * 8 + 2 * (lane & 3);
            zb[r0 * 34 + c0]           = d0[0];
            zb[r0 * 34 + c0 + 1]       = d0[1];
            zb[(r0 + 8) * 34 + c0]     = d0[2];
            zb[(r0 + 8) * 34 + c0 + 1] = d0[3];
            zb[r0 * 34 + c0 + 8]           = d1[0];
            zb[r0 * 34 + c0 + 9]           = d1[1];
            zb[(r0 + 8) * 34 + c0 + 8]     = d1[2];
            zb[(r0 + 8) * 34 + c0 + 9]     = d1[3];
        }
        __syncthreads();

        // ---- fused gates + cell update + stores (thread = batch row b) ----
        if (tid < 64) {
            const int b = tid;
            float hv[8];
            uint32_t hiw[4], low[4];
#pragma unroll
            for (int j = 0; j < 8; j++) {
                const float zi = zb[b * 34 + j]      + xg[0][j];
                const float zf = zb[b * 34 + 8 + j]  + xg[1][j];
                const float zg = zb[b * 34 + 16 + j] + xg[2][j];
                const float zo = zb[b * 34 + 24 + j] + xg[3][j];
                const float ig = sigm(zi), fg = sigm(zf);
                const float gg = sigm(zg), og = sigm(zo);
                const float cn = fg * creg[j] + ig * gg;
                creg[j] = cn;
                hv[j] = og * sigm(cn);
            }
            // bf16 hi/lo split of new h -> global (next step's A operand)
#pragma unroll
            for (int p = 0; p < 4; p++) {
                const __nv_bfloat16 h0b = __float2bfloat16_rn(hv[2 * p]);
                const __nv_bfloat16 h1b = __float2bfloat16_rn(hv[2 * p + 1]);
                const __nv_bfloat16 l0b =
                    __float2bfloat16_rn(hv[2 * p] - __bfloat162float(h0b));
                const __nv_bfloat16 l1b =
                    __float2bfloat16_rn(hv[2 * p + 1] - __bfloat162float(h1b));
                hiw[p] = (uint32_t)__bfloat16_as_ushort(h0b) |
                         ((uint32_t)__bfloat16_as_ushort(h1b) << 16);
                low[p] = (uint32_t)__bfloat16_as_ushort(l0b) |
                         ((uint32_t)__bfloat16_as_ushort(l1b) << 16);
            }
            *(uint4*)&g_hbf[dir][pr ^ 1][0][b][j0] =
                make_uint4(hiw[0], hiw[1], hiw[2], hiw[3]);
            *(uint4*)&g_hbf[dir][pr ^ 1][1][b][j0] =
                make_uint4(low[0], low[1], low[2], low[3]);
            // fp32 hidden sequence
            float* ho = hout + ((size_t)b * TT + t) * HH + j0;
            *(float4*)(ho)     = make_float4(hv[0], hv[1], hv[2], hv[3]);
            *(float4*)(ho + 4) = make_float4(hv[4], hv[5], hv[6], hv[7]);
            if (s == TT - 1) {   // final states straight to output
                float* hf = dout + OUT0 + dir * 65536 + b * HH + j0;
                float* cf = hf + 32768;
                *(float4*)(hf)     = make_float4(hv[0], hv[1], hv[2], hv[3]);
                *(float4*)(hf + 4) = make_float4(hv[4], hv[5], hv[6], hv[7]);
                *(float4*)(cf)     = make_float4(creg[0], creg[1], creg[2], creg[3]);
                *(float4*)(cf + 4) = make_float4(creg[4], creg[5], creg[6], creg[7]);
            }
        }

        // ---- publish + arrive ----
        __threadfence();
        __syncthreads();
        if (tid == 0) {
            unsigned v = atomicAdd(&g_bar_count, 1u);
            if (v == NCTA - 1) {
                atomicExch(&g_bar_count, 0u);
                __threadfence();
                atomicAdd(&g_bar_epoch, 1u);
            }
        }
    }
}

// ---------------- combine: out = 0.5*(h_f + h_b) ---------------------------
__global__ void combine_kernel(float* __restrict__ dout) {
    const int i = blockIdx.x * 256 + threadIdx.x;   // OUT0/4 float4 elems
    const float4 a = ((const float4*)&g_hout[0][0][0][0])[i];
    const float4 b = ((const float4*)&g_hout[1][0][0][0])[i];
    ((float4*)dout)[i] = make_float4(0.5f * (a.x + b.x), 0.5f * (a.y + b.y),
                                     0.5f * (a.z + b.z), 0.5f * (a.w + b.w));
}

// ---------------- launch ---------------------------------------------------
extern "C" void kernel_launch(void* const* d_in, const int* in_sizes, int n_in,
                              void* d_out, int out_size) {
    const float* x  = (const float*)d_in[0];
    // d_in[1] = hidden : unused by the reference (zero initial state)
    const float* Wf = (const float*)d_in[2];
    const float* Uf = (const float*)d_in[3];
    const float* bf = (const float*)d_in[4];
    const float* Wb = (const float*)d_in[5];
    const float* Ub = (const float*)d_in[6];
    const float* bb = (const float*)d_in[7];
    float* out = (float*)d_out;

    cudaFuncSetAttribute(lstm_persistent,
                         cudaFuncAttributeMaxDynamicSharedMemorySize, SMEM_TOTAL);

    // re-zero recurrent state + barrier every launch (graph replay safe)
    init_state_kernel<<<512, 256>>>();

    // input projection for both directions
    proj_kernel<<<dim3(MROWS / 128, G4H / 128, 2), 256>>>(x, Wf, bf, Wb, bb);

    // persistent tensor-core recurrence: one kernel, 512 steps, grid barrier
    lstm_persistent<<<dim3(64, 2), 256, SMEM_TOTAL>>>(Uf, Ub, out);

    // blend directions
    combine_kernel<<<OUT0 / 4 / 256, 256>>>(out);
}

// round 13
// speedup vs baseline: 2.2494x; 1.1573x over previous
#include <cuda_runtime.h>
#include <cuda_bf16.h>
#include <cstdint>

// Shapes (fixed)
#define BB 64
#define TT 512
#define DD 256
#define HH 512
#define G4H 2048           // 4*H
#define MROWS 32768        // B*T
#define OUT0 16777216      // B*T*H
#define NCTA 128           // persistent grid: 64 col-tiles x 2 dirs

// ---------------- device scratch ------------------------------------------
__device__ float g_xw[2][MROWS][G4H];               // x@W+b, row r = b*T + t
__device__ float g_hout[2][BB][TT][HH];             // per-direction hidden seq
__device__ __nv_bfloat16 g_hbf[2][2][2][BB][HH];    // [dir][pingpong][hi/lo][b][k]
__device__ __nv_bfloat16 g_xbf[2][MROWS][DD];       // [hi/lo][row][k]
__device__ __nv_bfloat16 g_wbf[2][2][G4H][DD];      // [dir][hi/lo][n][k]
__device__ unsigned g_bar_count;
__device__ unsigned g_bar_epoch;

__device__ __forceinline__ float sigm(float x) {
    return 1.0f / (1.0f + __expf(-x));
}

__device__ __forceinline__ uint32_t s2u(const void* p) {
    uint32_t a;
    asm("{ .reg .u64 t; cvta.to.shared.u64 t, %1; cvt.u32.u64 %0, t; }"
        : "=r"(a) : "l"(p));
    return a;
}

// ---- warp-level tensor ops (sm_80-baseline PTX; works on compute_103) ----
__device__ __forceinline__ void ldsm4(uint32_t* a, uint32_t addr) {
    asm volatile("ldmatrix.sync.aligned.m8n8.x4.shared.b16 {%0,%1,%2,%3}, [%4];"
                 : "=r"(a[0]), "=r"(a[1]), "=r"(a[2]), "=r"(a[3]) : "r"(addr));
}
__device__ __forceinline__ void ldsm2(uint32_t& b0, uint32_t& b1, uint32_t addr) {
    asm volatile("ldmatrix.sync.aligned.m8n8.x2.shared.b16 {%0,%1}, [%2];"
                 : "=r"(b0), "=r"(b1) : "r"(addr));
}
__device__ __forceinline__ void mma16816(float* d, const uint32_t* a,
                                         uint32_t b0, uint32_t b1) {
    asm volatile(
        "mma.sync.aligned.m16n8k16.row.col.f32.bf16.bf16.f32 "
        "{%0,%1,%2,%3}, {%4,%5,%6,%7}, {%8,%9}, {%0,%1,%2,%3};"
        : "+f"(d[0]), "+f"(d[1]), "+f"(d[2]), "+f"(d[3])
        : "r"(a[0]), "r"(a[1]), "r"(a[2]), "r"(a[3]), "r"(b0), "r"(b1));
}

__device__ __forceinline__ void split_pack(float v0, float v1,
                                           uint32_t& hiw, uint32_t& low) {
    const __nv_bfloat16 h0 = __float2bfloat16_rn(v0);
    const __nv_bfloat16 h1 = __float2bfloat16_rn(v1);
    const __nv_bfloat16 l0 = __float2bfloat16_rn(v0 - __bfloat162float(h0));
    const __nv_bfloat16 l1 = __float2bfloat16_rn(v1 - __bfloat162float(h1));
    hiw = (uint32_t)__bfloat16_as_ushort(h0) |
          ((uint32_t)__bfloat16_as_ushort(h1) << 16);
    low = (uint32_t)__bfloat16_as_ushort(l0) |
          ((uint32_t)__bfloat16_as_ushort(l1) << 16);
}

// ---------------- state init (replay-safe) --------------------------------
__global__ void init_state_kernel() {
    int i = blockIdx.x * blockDim.x + threadIdx.x;   // 131072 threads
    ((uint32_t*)&g_hbf[0][0][0][0][0])[i] = 0u;      // 512KB of bf16 zeros
    if (i == 0) { g_bar_count = 0u; g_bar_epoch = 0u; }
}

// ---------------- convert x -> bf16 hi/lo planes --------------------------
__global__ void convert_x_kernel(const float* __restrict__ x) {
    const int i = blockIdx.x * 256 + threadIdx.x;    // MROWS*DD/2 pairs
    const float2 v = ((const float2*)x)[i];
    uint32_t hiw, low;
    split_pack(v.x, v.y, hiw, low);
    ((uint32_t*)&g_xbf[0][0][0])[i] = hiw;
    ((uint32_t*)&g_xbf[1][0][0])[i] = low;
}

// ---------------- convert + transpose W -> g_wbf[dir][term][n][k] ---------
__global__ void convert_w_kernel(const float* __restrict__ Wf,
                                 const float* __restrict__ Wb) {
    __shared__ float tile[32][33];
    const float* W = blockIdx.z ? Wb : Wf;
    const int n0 = blockIdx.x * 32, k0 = blockIdx.y * 32;
    tile[threadIdx.y][threadIdx.x] =
        W[(size_t)(k0 + threadIdx.y) * G4H + n0 + threadIdx.x];
    __syncthreads();
    const int n = n0 + threadIdx.y, k = k0 + threadIdx.x;
    const float v = tile[threadIdx.x][threadIdx.y];
    const __nv_bfloat16 hi = __float2bfloat16_rn(v);
    const __nv_bfloat16 lo = __float2bfloat16_rn(v - __bfloat162float(hi));
    g_wbf[blockIdx.z][0][n][k] = hi;
    g_wbf[blockIdx.z][1][n][k] = lo;
}

// ---------------- tensor projection: g_xw = x @ W + b ---------------------
// CTA tile 128x128, K=256 in 4 chunks of 64. 8 warps (2x4), warp 64x32.
// 3 bf16 terms: xhi*whi + xhi*wlo + xlo*whi.
#define AST 72                      // smem stride in halfs (144B)
#define PA_TERM (128 * AST)         // halfs per term plane = 9216
#define PRJ_B  (2 * PA_TERM * 2)    // B planes start (bytes) = 36864  [FIXED]
#define PRJ_SMEM 73728              // A (36864) + B (36864)

__global__ __launch_bounds__(256, 1) void proj_mma_kernel(
    const float* __restrict__ bf, const float* __restrict__ bb) {
    extern __shared__ char smc[];
    const uint32_t smb = s2u(smc);

    const int mt = blockIdx.x, nt = blockIdx.y, dir = blockIdx.z;
    const float* bias = dir ? bb : bf;
    const int tid = threadIdx.x;
    const int w = tid >> 5, lane = tid & 31;
    const int mw = w >> 2, nw = w & 3;

    float d[4][4][4];
#pragma unroll
    for (int mb = 0; mb < 4; mb++)
#pragma unroll
        for (int nb = 0; nb < 4; nb++)
#pragma unroll
            for (int q = 0; q < 4; q++) d[mb][nb][q] = 0.0f;

    const uint32_t aBase = smb +
        (uint32_t)(((mw * 64 + (lane & 15)) * AST + ((lane >> 4) & 1) * 8) * 2);
    const uint32_t bBase = smb + PRJ_B +
        (uint32_t)(((nw * 32 + (lane & 7)) * AST + (lane & 8)) * 2);

    for (int kc = 0; kc < 4; ++kc) {
        // load A: 2048 uint4 (hi+lo planes, 128 rows x 64 halfs each)
#pragma unroll
        for (int q = 0; q < 8; ++q) {
            const int i = tid + q * 256;
            const int term = i >> 10, idx = i & 1023;
            const int r = idx >> 3, cq = idx & 7;
            const uint4 v = *(const uint4*)
                &g_xbf[term][mt * 128 + r][kc * 64 + cq * 8];
            *(uint4*)(smc + (term * PA_TERM + r * AST + cq * 8) * 2) = v;
        }
        // load B: 2048 uint4
#pragma unroll
        for (int q = 0; q < 8; ++q) {
            const int i = tid + q * 256;
            const int term = i >> 10, idx = i & 1023;
            const int r = idx >> 3, cq = idx & 7;
            const uint4 v = *(const uint4*)
                &g_wbf[dir][term][nt * 128 + r][kc * 64 + cq * 8];
            *(uint4*)(smc + PRJ_B + (term * PA_TERM + r * AST + cq * 8) * 2) = v;
        }
        __syncthreads();

#pragma unroll
        for (int k16 = 0; k16 < 4; ++k16) {
            const uint32_t ko = (uint32_t)(k16 * 16 * 2);
            uint32_t bh[4][2], bl[4][2];
#pragma unroll
            for (int nb = 0; nb < 4; ++nb) {
                const uint32_t ba = bBase + (uint32_t)(nb * 8 * AST * 2) + ko;
                ldsm2(bh[nb][0], bh[nb][1], ba);
                ldsm2(bl[nb][0], bl[nb][1], ba + PA_TERM * 2);
            }
#pragma unroll
            for (int mb = 0; mb < 4; ++mb) {
                uint32_t ah[4], al[4];
                const uint32_t aa = aBase + (uint32_t)(mb * 16 * AST * 2) + ko;
                ldsm4(ah, aa);
                ldsm4(al, aa + PA_TERM * 2);
#pragma unroll
                for (int nb = 0; nb < 4; ++nb) {
                    mma16816(d[mb][nb], ah, bh[nb][0], bh[nb][1]);
                    mma16816(d[mb][nb], ah, bl[nb][0], bl[nb][1]);
                    mma16816(d[mb][nb], al, bh[nb][0], bh[nb][1]);
                }
            }
        }
        __syncthreads();
    }

    // epilogue: add bias, store fp32
    const int r = lane >> 2, c2 = (lane & 3) * 2;
#pragma unroll
    for (int nb = 0; nb < 4; ++nb) {
        const int col = nt * 128 + nw * 32 + nb * 8 + c2;
        const float2 bv = *(const float2*)(bias + col);
#pragma unroll
        for (int mb = 0; mb < 4; ++mb) {
            const int row = mt * 128 + mw * 64 + mb * 16 + r;
            *(float2*)&g_xw[dir][row][col] =
                make_float2(d[mb][nb][0] + bv.x, d[mb][nb][1] + bv.y);
            *(float2*)&g_xw[dir][row + 8][col] =
                make_float2(d[mb][nb][2] + bv.x, d[mb][nb][3] + bv.y);
        }
    }
}

// ---------------- persistent tensor recurrence ----------------------------
// (identical to R11 passing kernel)
#define HSTR 520
#define HS_HI 0
#define HS_LO 66560
#define US_HI 133120
#define US_LO 166400
#define ZB    199680         // float zb[64][34]
#define SMEM_TOTAL 208384

__global__ __launch_bounds__(256, 1) void lstm_persistent(
    const float* __restrict__ Uf, const float* __restrict__ Ub,
    float* __restrict__ dout) {
    extern __shared__ char smc[];
    const uint32_t smb = s2u(smc);
    float* zb = (float*)(smc + ZB);

    const int dir = blockIdx.y;
    const int jt  = blockIdx.x;
    const int j0  = jt * 8;
    const int tid = threadIdx.x;
    const int w   = tid >> 5;
    const int lane = tid & 31;

    // ---- resident U slice as bf16 hi/lo, [n=32][k=512] row-major ----
    const float* U = dir ? Ub : Uf;
    for (int i = tid; i < 32 * 512; i += 256) {
        const int n = i >> 9, k = i & 511;
        const int gcol = ((n >> 3) << 9) + j0 + (n & 7);
        const float v = U[(size_t)k * G4H + gcol];
        const __nv_bfloat16 hi = __float2bfloat16_rn(v);
        const __nv_bfloat16 lo = __float2bfloat16_rn(v - __bfloat162float(hi));
        *(__nv_bfloat16*)(smc + US_HI + (n * HSTR + k) * 2) = hi;
        *(__nv_bfloat16*)(smc + US_LO + (n * HSTR + k) * 2) = lo;
    }

    const int mb  = w >> 1;
    const int nb0 = (w & 1) * 2;
    const uint32_t aoff = (uint32_t)(((mb * 16 + (lane & 15)) * HSTR +
                                      ((lane >> 4) & 1) * 8) * 2);
    const uint32_t aHi = smb + HS_HI + aoff;
    const uint32_t aLo = smb + HS_LO + aoff;
    const uint32_t boff = (uint32_t)(((nb0 * 8 + (lane & 7)) * HSTR +
                                      (lane & 8)) * 2);
    const uint32_t b0Hi = smb + US_HI + boff;
    const uint32_t b1Hi = b0Hi + 8 * HSTR * 2;
    const uint32_t b0Lo = smb + US_LO + boff;
    const uint32_t b1Lo = b0Lo + 8 * HSTR * 2;

    const float* xw = &g_xw[dir][0][0];
    float* hout = &g_hout[dir][0][0][0];

    float creg[8];
#pragma unroll
    for (int j = 0; j < 8; j++) creg[j] = 0.0f;

    __syncthreads();  // U ready

    for (int s = 0; s < TT; ++s) {
        if (tid == 0) {
            while (*((volatile unsigned*)&g_bar_epoch) < (unsigned)s) { }
        }
        __syncthreads();

        const int pr = s & 1;
        const int t = dir ? (TT - 1 - s) : s;

        float xg[4][8];
        if (tid < 64) {
            const float* xrow = xw + (size_t)(tid * TT + t) * G4H + j0;
#pragma unroll
            for (int g = 0; g < 4; g++) {
                float4 a = *(const float4*)(xrow + g * 512);
                float4 b = *(const float4*)(xrow + g * 512 + 4);
                xg[g][0] = a.x; xg[g][1] = a.y; xg[g][2] = a.z; xg[g][3] = a.w;
                xg[g][4] = b.x; xg[g][5] = b.y; xg[g][6] = b.z; xg[g][7] = b.w;
            }
        }

        {
            const uint4* src = (const uint4*)&g_hbf[dir][pr][0][0][0];
#pragma unroll
            for (int q = 0; q < 32; ++q) {
                const int i = tid + q * 256;
                const int m = i >> 12;
                const int r = (i >> 6) & 63;
                const int c16 = i & 63;
                uint4 v = src[i];
                *(uint4*)(smc + (m ? HS_LO : HS_HI) + (r * HSTR + c16 * 8) * 2) = v;
            }
        }
        __syncthreads();

        float d0[4] = {0.f, 0.f, 0.f, 0.f};
        float d1[4] = {0.f, 0.f, 0.f, 0.f};
#pragma unroll 4
        for (int k0 = 0; k0 < 512; k0 += 16) {
            const uint32_t ko = (uint32_t)(k0 * 2);
            uint32_t ah[4], al[4], bh0[2], bh1[2], bl0[2], bl1[2];
            ldsm4(ah, aHi + ko);
            ldsm2(bh0[0], bh0[1], b0Hi + ko);
            ldsm2(bh1[0], bh1[1], b1Hi + ko);
            ldsm2(bl0[0], bl0[1], b0Lo + ko);
            ldsm2(bl1[0], bl1[1], b1Lo + ko);
            ldsm4(al, aLo + ko);
            mma16816(d0, ah, bh0[0], bh0[1]);
            mma16816(d1, ah, bh1[0], bh1[1]);
            mma16816(d0, ah, bl0[0], bl0[1]);
            mma16816(d1, ah, bl1[0], bl1[1]);
            mma16816(d0, al, bh0[0], bh0[1]);
            mma16816(d1, al, bh1[0], bh1[1]);
        }

        {
            const int r0 = mb * 16 + (lane >> 2);
            const int c0 = nb0 * 8 + 2 * (lane & 3);
            zb[r0 * 34 + c0]           = d0[0];
            zb[r0 * 34 + c0 + 1]       = d0[1];
            zb[(r0 + 8) * 34 + c0]     = d0[2];
            zb[(r0 + 8) * 34 + c0 + 1] = d0[3];
            zb[r0 * 34 + c0 + 8]           = d1[0];
            zb[r0 * 34 + c0 + 9]           = d1[1];
            zb[(r0 + 8) * 34 + c0 + 8]     = d1[2];
            zb[(r0 + 8) * 34 + c0 + 9]     = d1[3];
        }
        __syncthreads();

        if (tid < 64) {
            const int b = tid;
            float hv[8];
            uint32_t hiw[4], low[4];
#pragma unroll
            for (int j = 0; j < 8; j++) {
                const float zi = zb[b * 34 + j]      + xg[0][j];
                const float zf = zb[b * 34 + 8 + j]  + xg[1][j];
                const float zg = zb[b * 34 + 16 + j] + xg[2][j];
                const float zo = zb[b * 34 + 24 + j] + xg[3][j];
                const float ig = sigm(zi), fg = sigm(zf);
                const float gg = sigm(zg), og = sigm(zo);
                const float cn = fg * creg[j] + ig * gg;
                creg[j] = cn;
                hv[j] = og * sigm(cn);
            }
#pragma unroll
            for (int p = 0; p < 4; p++)
                split_pack(hv[2 * p], hv[2 * p + 1], hiw[p], low[p]);
            *(uint4*)&g_hbf[dir][pr ^ 1][0][b][j0] =
                make_uint4(hiw[0], hiw[1], hiw[2], hiw[3]);
            *(uint4*)&g_hbf[dir][pr ^ 1][1][b][j0] =
                make_uint4(low[0], low[1], low[2], low[3]);
            float* ho = hout + ((size_t)b * TT + t) * HH + j0;
            *(float4*)(ho)     = make_float4(hv[0], hv[1], hv[2], hv[3]);
            *(float4*)(ho + 4) = make_float4(hv[4], hv[5], hv[6], hv[7]);
            if (s == TT - 1) {
                float* hf = dout + OUT0 + dir * 65536 + b * HH + j0;
                float* cf = hf + 32768;
                *(float4*)(hf)     = make_float4(hv[0], hv[1], hv[2], hv[3]);
                *(float4*)(hf + 4) = make_float4(hv[4], hv[5], hv[6], hv[7]);
                *(float4*)(cf)     = make_float4(creg[0], creg[1], creg[2], creg[3]);
                *(float4*)(cf + 4) = make_float4(creg[4], creg[5], creg[6], creg[7]);
            }
        }

        __threadfence();
        __syncthreads();
        if (tid == 0) {
            unsigned v = atomicAdd(&g_bar_count, 1u);
            if (v == NCTA - 1) {
                atomicExch(&g_bar_count, 0u);
                __threadfence();
                atomicAdd(&g_bar_epoch, 1u);
            }
        }
    }
}

// ---------------- combine: out = 0.5*(h_f + h_b) ---------------------------
__global__ void combine_kernel(float* __restrict__ dout) {
    const int i = blockIdx.x * 256 + threadIdx.x;   // OUT0/4 float4 elems
    const float4 a = ((const float4*)&g_hout[0][0][0][0])[i];
    const float4 b = ((const float4*)&g_hout[1][0][0][0])[i];
    ((float4*)dout)[i] = make_float4(0.5f * (a.x + b.x), 0.5f * (a.y + b.y),
                                     0.5f * (a.z + b.z), 0.5f * (a.w + b.w));
}

// ---------------- launch ---------------------------------------------------
extern "C" void kernel_launch(void* const* d_in, const int* in_sizes, int n_in,
                              void* d_out, int out_size) {
    const float* x  = (const float*)d_in[0];
    // d_in[1] = hidden : unused by the reference (zero initial state)
    const float* Wf = (const float*)d_in[2];
    const float* Uf = (const float*)d_in[3];
    const float* bf = (const float*)d_in[4];
    const float* Wb = (const float*)d_in[5];
    const float* Ub = (const float*)d_in[6];
    const float* bb = (const float*)d_in[7];
    float* out = (float*)d_out;

    cudaFuncSetAttribute(lstm_persistent,
                         cudaFuncAttributeMaxDynamicSharedMemorySize, SMEM_TOTAL);
    cudaFuncSetAttribute(proj_mma_kernel,
                         cudaFuncAttributeMaxDynamicSharedMemorySize, PRJ_SMEM);

    // re-zero recurrent state + barrier every launch (graph replay safe)
    init_state_kernel<<<512, 256>>>();

    // bf16 hi/lo conversion of x and W (transposed)
    convert_x_kernel<<<MROWS * DD / 2 / 256, 256>>>(x);
    convert_w_kernel<<<dim3(G4H / 32, DD / 32, 2), dim3(32, 32)>>>(Wf, Wb);

    // tensor-core input projection for both directions
    proj_mma_kernel<<<dim3(MROWS / 128, G4H / 128, 2), 256, PRJ_SMEM>>>(bf, bb);

    // persistent tensor-core recurrence: one kernel, 512 steps, grid barrier
    lstm_persistent<<<dim3(64, 2), 256, SMEM_TOTAL>>>(Uf, Ub, out);

    // blend directions
    combine_kernel<<<OUT0 / 4 / 256, 256>>>(out);
}

// round 14
// speedup vs baseline: 2.4784x; 1.1018x over previous
#include <cuda_runtime.h>
#include <cuda_bf16.h>
#include <cstdint>

// Shapes (fixed)
#define BB 64
#define TT 512
#define DD 256
#define HH 512
#define G4H 2048           // 4*H
#define MROWS 32768        // B*T
#define OUT0 16777216      // B*T*H
#define NCTA 128           // persistent grid: 64 col-tiles x 2 dirs

// ---------------- device scratch ------------------------------------------
__device__ float g_xw[2][MROWS][G4H];               // x@W+b, row r = b*T + t
__device__ __nv_bfloat16 g_hbf[2][2][2][BB][HH];    // [dir][pingpong][hi/lo][b][k]
__device__ __nv_bfloat16 g_xbf[2][MROWS][DD];       // [hi/lo][row][k]
__device__ __nv_bfloat16 g_wbf[2][2][G4H][DD];      // [dir][hi/lo][n][k]
__device__ unsigned g_flags[NCTA];                  // distributed barrier flags

__device__ __forceinline__ float sigm(float x) {
    return 1.0f / (1.0f + __expf(-x));
}

__device__ __forceinline__ uint32_t s2u(const void* p) {
    uint32_t a;
    asm("{ .reg .u64 t; cvta.to.shared.u64 t, %1; cvt.u32.u64 %0, t; }"
        : "=r"(a) : "l"(p));
    return a;
}

// ---- warp-level tensor ops (sm_80-baseline PTX; works on compute_103) ----
__device__ __forceinline__ void ldsm4(uint32_t* a, uint32_t addr) {
    asm volatile("ldmatrix.sync.aligned.m8n8.x4.shared.b16 {%0,%1,%2,%3}, [%4];"
                 : "=r"(a[0]), "=r"(a[1]), "=r"(a[2]), "=r"(a[3]) : "r"(addr));
}
__device__ __forceinline__ void ldsm2(uint32_t& b0, uint32_t& b1, uint32_t addr) {
    asm volatile("ldmatrix.sync.aligned.m8n8.x2.shared.b16 {%0,%1}, [%2];"
                 : "=r"(b0), "=r"(b1) : "r"(addr));
}
__device__ __forceinline__ void mma16816(float* d, const uint32_t* a,
                                         uint32_t b0, uint32_t b1) {
    asm volatile(
        "mma.sync.aligned.m16n8k16.row.col.f32.bf16.bf16.f32 "
        "{%0,%1,%2,%3}, {%4,%5,%6,%7}, {%8,%9}, {%0,%1,%2,%3};"
        : "+f"(d[0]), "+f"(d[1]), "+f"(d[2]), "+f"(d[3])
        : "r"(a[0]), "r"(a[1]), "r"(a[2]), "r"(a[3]), "r"(b0), "r"(b1));
}

__device__ __forceinline__ void cpasync16(uint32_t dst, const void* src) {
    asm volatile("cp.async.cg.shared.global [%0], [%1], 16;"
                 :: "r"(dst), "l"(src) : "memory");
}
#define CP_COMMIT() asm volatile("cp.async.commit_group;" ::: "memory")
#define CP_WAIT(n)  asm volatile("cp.async.wait_group %0;" :: "n"(n) : "memory")

__device__ __forceinline__ void split_pack(float v0, float v1,
                                           uint32_t& hiw, uint32_t& low) {
    const __nv_bfloat16 h0 = __float2bfloat16_rn(v0);
    const __nv_bfloat16 h1 = __float2bfloat16_rn(v1);
    const __nv_bfloat16 l0 = __float2bfloat16_rn(v0 - __bfloat162float(h0));
    const __nv_bfloat16 l1 = __float2bfloat16_rn(v1 - __bfloat162float(h1));
    hiw = (uint32_t)__bfloat16_as_ushort(h0) |
          ((uint32_t)__bfloat16_as_ushort(h1) << 16);
    low = (uint32_t)__bfloat16_as_ushort(l0) |
          ((uint32_t)__bfloat16_as_ushort(l1) << 16);
}

// ---------------- state init (replay-safe) --------------------------------
__global__ void init_state_kernel() {
    int i = blockIdx.x * blockDim.x + threadIdx.x;   // 131072 threads
    ((uint32_t*)&g_hbf[0][0][0][0][0])[i] = 0u;      // 512KB of bf16 zeros
    if (i < NCTA) g_flags[i] = 0u;
}

// ---------------- convert x -> bf16 hi/lo planes --------------------------
__global__ void convert_x_kernel(const float* __restrict__ x) {
    const int i = blockIdx.x * 256 + threadIdx.x;    // MROWS*DD/2 pairs
    const float2 v = ((const float2*)x)[i];
    uint32_t hiw, low;
    split_pack(v.x, v.y, hiw, low);
    ((uint32_t*)&g_xbf[0][0][0])[i] = hiw;
    ((uint32_t*)&g_xbf[1][0][0])[i] = low;
}

// ---------------- convert + transpose W -> g_wbf[dir][term][n][k] ---------
__global__ void convert_w_kernel(const float* __restrict__ Wf,
                                 const float* __restrict__ Wb) {
    __shared__ float tile[32][33];
    const float* W = blockIdx.z ? Wb : Wf;
    const int n0 = blockIdx.x * 32, k0 = blockIdx.y * 32;
    tile[threadIdx.y][threadIdx.x] =
        W[(size_t)(k0 + threadIdx.y) * G4H + n0 + threadIdx.x];
    __syncthreads();
    const int n = n0 + threadIdx.y, k = k0 + threadIdx.x;
    const float v = tile[threadIdx.x][threadIdx.y];
    const __nv_bfloat16 hi = __float2bfloat16_rn(v);
    const __nv_bfloat16 lo = __float2bfloat16_rn(v - __bfloat162float(hi));
    g_wbf[blockIdx.z][0][n][k] = hi;
    g_wbf[blockIdx.z][1][n][k] = lo;
}

// ---------------- tensor projection: g_xw = x @ W + b ---------------------
// (identical to R13 passing kernel)
#define AST 72                      // smem stride in halfs (144B)
#define PA_TERM (128 * AST)         // halfs per term plane = 9216
#define PRJ_B  (2 * PA_TERM * 2)    // B planes start (bytes) = 36864
#define PRJ_SMEM 73728              // A (36864) + B (36864)

__global__ __launch_bounds__(256, 1) void proj_mma_kernel(
    const float* __restrict__ bf, const float* __restrict__ bb) {
    extern __shared__ char smc[];
    const uint32_t smb = s2u(smc);

    const int mt = blockIdx.x, nt = blockIdx.y, dir = blockIdx.z;
    const float* bias = dir ? bb : bf;
    const int tid = threadIdx.x;
    const int w = tid >> 5, lane = tid & 31;
    const int mw = w >> 2, nw = w & 3;

    float d[4][4][4];
#pragma unroll
    for (int mb = 0; mb < 4; mb++)
#pragma unroll
        for (int nb = 0; nb < 4; nb++)
#pragma unroll
            for (int q = 0; q < 4; q++) d[mb][nb][q] = 0.0f;

    const uint32_t aBase = smb +
        (uint32_t)(((mw * 64 + (lane & 15)) * AST + ((lane >> 4) & 1) * 8) * 2);
    const uint32_t bBase = smb + PRJ_B +
        (uint32_t)(((nw * 32 + (lane & 7)) * AST + (lane & 8)) * 2);

    for (int kc = 0; kc < 4; ++kc) {
#pragma unroll
        for (int q = 0; q < 8; ++q) {
            const int i = tid + q * 256;
            const int term = i >> 10, idx = i & 1023;
            const int r = idx >> 3, cq = idx & 7;
            const uint4 v = *(const uint4*)
                &g_xbf[term][mt * 128 + r][kc * 64 + cq * 8];
            *(uint4*)(smc + (term * PA_TERM + r * AST + cq * 8) * 2) = v;
        }
#pragma unroll
        for (int q = 0; q < 8; ++q) {
            const int i = tid + q * 256;
            const int term = i >> 10, idx = i & 1023;
            const int r = idx >> 3, cq = idx & 7;
            const uint4 v = *(const uint4*)
                &g_wbf[dir][term][nt * 128 + r][kc * 64 + cq * 8];
            *(uint4*)(smc + PRJ_B + (term * PA_TERM + r * AST + cq * 8) * 2) = v;
        }
        __syncthreads();

#pragma unroll
        for (int k16 = 0; k16 < 4; ++k16) {
            const uint32_t ko = (uint32_t)(k16 * 16 * 2);
            uint32_t bh[4][2], bl[4][2];
#pragma unroll
            for (int nb = 0; nb < 4; ++nb) {
                const uint32_t ba = bBase + (uint32_t)(nb * 8 * AST * 2) + ko;
                ldsm2(bh[nb][0], bh[nb][1], ba);
                ldsm2(bl[nb][0], bl[nb][1], ba + PA_TERM * 2);
            }
#pragma unroll
            for (int mb = 0; mb < 4; ++mb) {
                uint32_t ah[4], al[4];
                const uint32_t aa = aBase + (uint32_t)(mb * 16 * AST * 2) + ko;
                ldsm4(ah, aa);
                ldsm4(al, aa + PA_TERM * 2);
#pragma unroll
                for (int nb = 0; nb < 4; ++nb) {
                    mma16816(d[mb][nb], ah, bh[nb][0], bh[nb][1]);
                    mma16816(d[mb][nb], ah, bl[nb][0], bl[nb][1]);
                    mma16816(d[mb][nb], al, bh[nb][0], bh[nb][1]);
                }
            }
        }
        __syncthreads();
    }

    const int r = lane >> 2, c2 = (lane & 3) * 2;
#pragma unroll
    for (int nb = 0; nb < 4; ++nb) {
        const int col = nt * 128 + nw * 32 + nb * 8 + c2;
        const float2 bv = *(const float2*)(bias + col);
#pragma unroll
        for (int mb = 0; mb < 4; ++mb) {
            const int row = mt * 128 + mw * 64 + mb * 16 + r;
            *(float2*)&g_xw[dir][row][col] =
                make_float2(d[mb][nb][0] + bv.x, d[mb][nb][1] + bv.y);
            *(float2*)&g_xw[dir][row + 8][col] =
                make_float2(d[mb][nb][2] + bv.x, d[mb][nb][3] + bv.y);
        }
    }
}

// ---------------- persistent tensor recurrence ----------------------------
#define HSTR 520
#define HS_HI 0
#define HS_LO 66560
#define US_HI 133120
#define US_LO 166400
#define ZB    199680         // float zb[64][34]
#define SMEM_TOTAL 208384

__global__ __launch_bounds__(256, 1) void lstm_persistent(
    const float* __restrict__ Uf, const float* __restrict__ Ub,
    float* __restrict__ dout) {
    extern __shared__ char smc[];
    const uint32_t smb = s2u(smc);
    float* zb = (float*)(smc + ZB);

    const int dir = blockIdx.y;
    const int jt  = blockIdx.x;
    const int j0  = jt * 8;
    const int cid = dir * 64 + jt;
    const int tid = threadIdx.x;
    const int w   = tid >> 5;
    const int lane = tid & 31;

    // ---- resident U slice as bf16 hi/lo, [n=32][k=512] row-major ----
    const float* U = dir ? Ub : Uf;
    for (int i = tid; i < 32 * 512; i += 256) {
        const int n = i >> 9, k = i & 511;
        const int gcol = ((n >> 3) << 9) + j0 + (n & 7);
        const float v = U[(size_t)k * G4H + gcol];
        const __nv_bfloat16 hi = __float2bfloat16_rn(v);
        const __nv_bfloat16 lo = __float2bfloat16_rn(v - __bfloat162float(hi));
        *(__nv_bfloat16*)(smc + US_HI + (n * HSTR + k) * 2) = hi;
        *(__nv_bfloat16*)(smc + US_LO + (n * HSTR + k) * 2) = lo;
    }

    const int mb  = w >> 1;
    const int nb0 = (w & 1) * 2;
    const uint32_t aoff = (uint32_t)(((mb * 16 + (lane & 15)) * HSTR +
                                      ((lane >> 4) & 1) * 8) * 2);
    const uint32_t aHi = smb + HS_HI + aoff;
    const uint32_t aLo = smb + HS_LO + aoff;
    const uint32_t boff = (uint32_t)(((nb0 * 8 + (lane & 7)) * HSTR +
                                      (lane & 8)) * 2);
    const uint32_t b0Hi = smb + US_HI + boff;
    const uint32_t b1Hi = b0Hi + 8 * HSTR * 2;
    const uint32_t b0Lo = smb + US_LO + boff;
    const uint32_t b1Lo = b0Lo + 8 * HSTR * 2;

    const float* xw = &g_xw[dir][0][0];

    float creg[8];
#pragma unroll
    for (int j = 0; j < 8; j++) creg[j] = 0.0f;

    __syncthreads();  // U ready

    for (int s = 0; s < TT; ++s) {
        // ---- distributed flag barrier: wait for all CTAs at step s ----
        if (tid < NCTA) {
            volatile unsigned* fl = g_flags;
            while (fl[tid] < (unsigned)s) { }
        }
        __syncthreads();

        const int pr = s & 1;
        const int t = dir ? (TT - 1 - s) : s;

        // ---- issue cp.async h copy, both K-halves (L2-coherent) ----
        {
            const uint4* src = (const uint4*)&g_hbf[dir][pr][0][0][0];
#pragma unroll
            for (int hf = 0; hf < 2; ++hf) {
#pragma unroll
                for (int q = 0; q < 16; ++q) {
                    const int i = tid + q * 256;       // 0..4095
                    const int m = i >> 11;             // plane hi/lo
                    const int r = (i >> 5) & 63;
                    const int c16 = i & 31;
                    const uint4* s4 = src + (m * 4096 + r * 64 + hf * 32 + c16);
                    const uint32_t d = smb + (m ? HS_LO : HS_HI) +
                        (uint32_t)((r * HSTR + hf * 256 + c16 * 8) * 2);
                    cpasync16(d, s4);
                }
                CP_COMMIT();
            }
        }

        // ---- epilogue operand prefetch (warps 0,1: thread = batch row) ----
        float xg[4][8];
        if (tid < 64) {
            const float* xrow = xw + (size_t)(tid * TT + t) * G4H + j0;
#pragma unroll
            for (int g = 0; g < 4; g++) {
                float4 a = *(const float4*)(xrow + g * 512);
                float4 b = *(const float4*)(xrow + g * 512 + 4);
                xg[g][0] = a.x; xg[g][1] = a.y; xg[g][2] = a.z; xg[g][3] = a.w;
                xg[g][4] = b.x; xg[g][5] = b.y; xg[g][6] = b.z; xg[g][7] = b.w;
            }
        }

        // ---- tensor GEMM pipelined against the copy: 2 K-halves ----
        float d0[4] = {0.f, 0.f, 0.f, 0.f};
        float d1[4] = {0.f, 0.f, 0.f, 0.f};

        CP_WAIT(1);           // half 0 landed (all threads after barrier)
        __syncthreads();
#pragma unroll 4
        for (int k0 = 0; k0 < 256; k0 += 16) {
            const uint32_t ko = (uint32_t)(k0 * 2);
            uint32_t ah[4], al[4], bh0[2], bh1[2], bl0[2], bl1[2];
            ldsm4(ah, aHi + ko);
            ldsm2(bh0[0], bh0[1], b0Hi + ko);
            ldsm2(bh1[0], bh1[1], b1Hi + ko);
            ldsm2(bl0[0], bl0[1], b0Lo + ko);
            ldsm2(bl1[0], bl1[1], b1Lo + ko);
            ldsm4(al, aLo + ko);
            mma16816(d0, ah, bh0[0], bh0[1]);
            mma16816(d1, ah, bh1[0], bh1[1]);
            mma16816(d0, ah, bl0[0], bl0[1]);
            mma16816(d1, ah, bl1[0], bl1[1]);
            mma16816(d0, al, bh0[0], bh0[1]);
            mma16816(d1, al, bh1[0], bh1[1]);
        }
        CP_WAIT(0);           // half 1 landed
        __syncthreads();
#pragma unroll 4
        for (int k0 = 256; k0 < 512; k0 += 16) {
            const uint32_t ko = (uint32_t)(k0 * 2);
            uint32_t ah[4], al[4], bh0[2], bh1[2], bl0[2], bl1[2];
            ldsm4(ah, aHi + ko);
            ldsm2(bh0[0], bh0[1], b0Hi + ko);
            ldsm2(bh1[0], bh1[1], b1Hi + ko);
            ldsm2(bl0[0], bl0[1], b0Lo + ko);
            ldsm2(bl1[0], bl1[1], b1Lo + ko);
            ldsm4(al, aLo + ko);
            mma16816(d0, ah, bh0[0], bh0[1]);
            mma16816(d1, ah, bh1[0], bh1[1]);
            mma16816(d0, ah, bl0[0], bl0[1]);
            mma16816(d1, ah, bl1[0], bl1[1]);
            mma16816(d0, al, bh0[0], bh0[1]);
            mma16816(d1, al, bh1[0], bh1[1]);
        }

        // ---- exchange accumulators through zb[64][34] ----
        {
            const int r0 = mb * 16 + (lane >> 2);
            const int c0 = nb0 * 8 + 2 * (lane & 3);
            zb[r0 * 34 + c0]           = d0[0];
            zb[r0 * 34 + c0 + 1]       = d0[1];
            zb[(r0 + 8) * 34 + c0]     = d0[2];
            zb[(r0 + 8) * 34 + c0 + 1] = d0[3];
            zb[r0 * 34 + c0 + 8]           = d1[0];
            zb[r0 * 34 + c0 + 9]           = d1[1];
            zb[(r0 + 8) * 34 + c0 + 8]     = d1[2];
            zb[(r0 + 8) * 34 + c0 + 9]     = d1[3];
        }
        __syncthreads();

        // ---- fused gates + cell update + stores (thread = batch row b) ----
        if (tid < 64) {
            const int b = tid;
            float hv[8];
            uint32_t hiw[4], low[4];
#pragma unroll
            for (int j = 0; j < 8; j++) {
                const float zi = zb[b * 34 + j]      + xg[0][j];
                const float zf = zb[b * 34 + 8 + j]  + xg[1][j];
                const float zg = zb[b * 34 + 16 + j] + xg[2][j];
                const float zo = zb[b * 34 + 24 + j] + xg[3][j];
                const float ig = sigm(zi), fg = sigm(zf);
                const float gg = sigm(zg), og = sigm(zo);
                const float cn = fg * creg[j] + ig * gg;
                creg[j] = cn;
                hv[j] = og * sigm(cn);
            }
#pragma unroll
            for (int p = 0; p < 4; p++)
                split_pack(hv[2 * p], hv[2 * p + 1], hiw[p], low[p]);
            *(uint4*)&g_hbf[dir][pr ^ 1][0][b][j0] =
                make_uint4(hiw[0], hiw[1], hiw[2], hiw[3]);
            *(uint4*)&g_hbf[dir][pr ^ 1][1][b][j0] =
                make_uint4(low[0], low[1], low[2], low[3]);

            // direct output: first writer (s<256) stores, second accumulates.
            // fwd writes t=s, bwd t=511-s: never the same t in one step; the
            // shared barrier orders cross-step writers.
            float* dp = dout + ((size_t)b * TT + t) * HH + j0;
            float4 o0 = make_float4(0.5f * hv[0], 0.5f * hv[1],
                                    0.5f * hv[2], 0.5f * hv[3]);
            float4 o1 = make_float4(0.5f * hv[4], 0.5f * hv[5],
                                    0.5f * hv[6], 0.5f * hv[7]);
            if (s >= 256) {
                const float4 p0 = __ldcg((const float4*)dp);
                const float4 p1 = __ldcg((const float4*)(dp + 4));
                o0.x += p0.x; o0.y += p0.y; o0.z += p0.z; o0.w += p0.w;
                o1.x += p1.x; o1.y += p1.y; o1.z += p1.z; o1.w += p1.w;
            }
            *(float4*)(dp)     = o0;
            *(float4*)(dp + 4) = o1;

            if (s == TT - 1) {   // final states straight to output
                float* hf = dout + OUT0 + dir * 65536 + b * HH + j0;
                float* cf = hf + 32768;
                *(float4*)(hf)     = make_float4(hv[0], hv[1], hv[2], hv[3]);
                *(float4*)(hf + 4) = make_float4(hv[4], hv[5], hv[6], hv[7]);
                *(float4*)(cf)     = make_float4(creg[0], creg[1], creg[2], creg[3]);
                *(float4*)(cf + 4) = make_float4(creg[4], creg[5], creg[6], creg[7]);
            }
        }

        // ---- publish + arrive: own flag, distinct address per CTA ----
        __threadfence();
        __syncthreads();
        if (tid == 0) atomicExch(&g_flags[cid], (unsigned)(s + 1));
    }
}

// ---------------- launch ---------------------------------------------------
extern "C" void kernel_launch(void* const* d_in, const int* in_sizes, int n_in,
                              void* d_out, int out_size) {
    const float* x  = (const float*)d_in[0];
    // d_in[1] = hidden : unused by the reference (zero initial state)
    const float* Wf = (const float*)d_in[2];
    const float* Uf = (const float*)d_in[3];
    const float* bf = (const float*)d_in[4];
    const float* Wb = (const float*)d_in[5];
    const float* Ub = (const float*)d_in[6];
    const float* bb = (const float*)d_in[7];
    float* out = (float*)d_out;

    cudaFuncSetAttribute(lstm_persistent,
                         cudaFuncAttributeMaxDynamicSharedMemorySize, SMEM_TOTAL);
    cudaFuncSetAttribute(proj_mma_kernel,
                         cudaFuncAttributeMaxDynamicSharedMemorySize, PRJ_SMEM);

    // re-zero recurrent state + flags every launch (graph replay safe)
    init_state_kernel<<<512, 256>>>();

    // bf16 hi/lo conversion of x and W (transposed)
    convert_x_kernel<<<MROWS * DD / 2 / 256, 256>>>(x);
    convert_w_kernel<<<dim3(G4H / 32, DD / 32, 2), dim3(32, 32)>>>(Wf, Wb);

    // tensor-core input projection for both directions
    proj_mma_kernel<<<dim3(MROWS / 128, G4H / 128, 2), 256, PRJ_SMEM>>>(bf, bb);

    // persistent tensor-core recurrence: one kernel, 512 steps, flag barrier
    lstm_persistent<<<dim3(64, 2), 256, SMEM_TOTAL>>>(Uf, Ub, out);
}

// round 15
// speedup vs baseline: 2.8026x; 1.1308x over previous
#include <cuda_runtime.h>
#include <cuda_bf16.h>
#include <cstdint>

// Shapes (fixed)
#define BB 64
#define TT 512
#define DD 256
#define HH 512
#define G4H 2048           // 4*H
#define MROWS 32768        // B*T
#define OUT0 16777216      // B*T*H
#define NCTA 128           // persistent grid: 64 col-tiles x 2 dirs

// ---------------- device scratch ------------------------------------------
__device__ float g_xw[2][MROWS][G4H];               // x@W+b, row r = b*T + t
__device__ __nv_bfloat16 g_hbf[2][2][2][BB][HH];    // [dir][pingpong][hi/lo][b][k]
__device__ __nv_bfloat16 g_xbf[2][MROWS][DD];       // [hi/lo][row][k]
__device__ __nv_bfloat16 g_wbf[2][2][G4H][DD];      // [dir][hi/lo][n][k]
__device__ unsigned g_flags[NCTA];                  // distributed barrier flags

__device__ __forceinline__ float sigm(float x) {
    return 1.0f / (1.0f + __expf(-x));
}

__device__ __forceinline__ uint32_t s2u(const void* p) {
    uint32_t a;
    asm("{ .reg .u64 t; cvta.to.shared.u64 t, %1; cvt.u32.u64 %0, t; }"
        : "=r"(a) : "l"(p));
    return a;
}

// ---- warp-level tensor ops (sm_80-baseline PTX; works on compute_103) ----
__device__ __forceinline__ void ldsm4(uint32_t* a, uint32_t addr) {
    asm volatile("ldmatrix.sync.aligned.m8n8.x4.shared.b16 {%0,%1,%2,%3}, [%4];"
                 : "=r"(a[0]), "=r"(a[1]), "=r"(a[2]), "=r"(a[3]) : "r"(addr));
}
__device__ __forceinline__ void ldsm2(uint32_t& b0, uint32_t& b1, uint32_t addr) {
    asm volatile("ldmatrix.sync.aligned.m8n8.x2.shared.b16 {%0,%1}, [%2];"
                 : "=r"(b0), "=r"(b1) : "r"(addr));
}
__device__ __forceinline__ void mma16816(float* d, const uint32_t* a,
                                         uint32_t b0, uint32_t b1) {
    asm volatile(
        "mma.sync.aligned.m16n8k16.row.col.f32.bf16.bf16.f32 "
        "{%0,%1,%2,%3}, {%4,%5,%6,%7}, {%8,%9}, {%0,%1,%2,%3};"
        : "+f"(d[0]), "+f"(d[1]), "+f"(d[2]), "+f"(d[3])
        : "r"(a[0]), "r"(a[1]), "r"(a[2]), "r"(a[3]), "r"(b0), "r"(b1));
}

__device__ __forceinline__ void cpasync16(uint32_t dst, const void* src) {
    asm volatile("cp.async.cg.shared.global [%0], [%1], 16;"
                 :: "r"(dst), "l"(src) : "memory");
}
#define CP_COMMIT() asm volatile("cp.async.commit_group;" ::: "memory")
#define CP_WAIT(n)  asm volatile("cp.async.wait_group %0;" :: "n"(n) : "memory")

__device__ __forceinline__ void split_pack(float v0, float v1,
                                           uint32_t& hiw, uint32_t& low) {
    const __nv_bfloat16 h0 = __float2bfloat16_rn(v0);
    const __nv_bfloat16 h1 = __float2bfloat16_rn(v1);
    const __nv_bfloat16 l0 = __float2bfloat16_rn(v0 - __bfloat162float(h0));
    const __nv_bfloat16 l1 = __float2bfloat16_rn(v1 - __bfloat162float(h1));
    hiw = (uint32_t)__bfloat16_as_ushort(h0) |
          ((uint32_t)__bfloat16_as_ushort(h1) << 16);
    low = (uint32_t)__bfloat16_as_ushort(l0) |
          ((uint32_t)__bfloat16_as_ushort(l1) << 16);
}

// ---------------- state init (replay-safe) --------------------------------
__global__ void init_state_kernel() {
    int i = blockIdx.x * blockDim.x + threadIdx.x;   // 131072 threads
    ((uint32_t*)&g_hbf[0][0][0][0][0])[i] = 0u;      // 512KB of bf16 zeros
    if (i < NCTA) g_flags[i] = 0u;
}

// ---------------- convert x -> bf16 hi/lo planes --------------------------
__global__ void convert_x_kernel(const float* __restrict__ x) {
    const int i = blockIdx.x * 256 + threadIdx.x;    // MROWS*DD/2 pairs
    const float2 v = ((const float2*)x)[i];
    uint32_t hiw, low;
    split_pack(v.x, v.y, hiw, low);
    ((uint32_t*)&g_xbf[0][0][0])[i] = hiw;
    ((uint32_t*)&g_xbf[1][0][0])[i] = low;
}

// ---------------- convert + transpose W -> g_wbf[dir][term][n][k] ---------
__global__ void convert_w_kernel(const float* __restrict__ Wf,
                                 const float* __restrict__ Wb) {
    __shared__ float tile[32][33];
    const float* W = blockIdx.z ? Wb : Wf;
    const int n0 = blockIdx.x * 32, k0 = blockIdx.y * 32;
    tile[threadIdx.y][threadIdx.x] =
        W[(size_t)(k0 + threadIdx.y) * G4H + n0 + threadIdx.x];
    __syncthreads();
    const int n = n0 + threadIdx.y, k = k0 + threadIdx.x;
    const float v = tile[threadIdx.x][threadIdx.y];
    const __nv_bfloat16 hi = __float2bfloat16_rn(v);
    const __nv_bfloat16 lo = __float2bfloat16_rn(v - __bfloat162float(hi));
    g_wbf[blockIdx.z][0][n][k] = hi;
    g_wbf[blockIdx.z][1][n][k] = lo;
}

// ---------------- tensor projection: g_xw = x @ W + b ---------------------
// (identical to R13/R14 passing kernel)
#define AST 72                      // smem stride in halfs (144B)
#define PA_TERM (128 * AST)         // halfs per term plane = 9216
#define PRJ_B  (2 * PA_TERM * 2)    // B planes start (bytes) = 36864
#define PRJ_SMEM 73728              // A (36864) + B (36864)

__global__ __launch_bounds__(256, 1) void proj_mma_kernel(
    const float* __restrict__ bf, const float* __restrict__ bb) {
    extern __shared__ char smc[];
    const uint32_t smb = s2u(smc);

    const int mt = blockIdx.x, nt = blockIdx.y, dir = blockIdx.z;
    const float* bias = dir ? bb : bf;
    const int tid = threadIdx.x;
    const int w = tid >> 5, lane = tid & 31;
    const int mw = w >> 2, nw = w & 3;

    float d[4][4][4];
#pragma unroll
    for (int mb = 0; mb < 4; mb++)
#pragma unroll
        for (int nb = 0; nb < 4; nb++)
#pragma unroll
            for (int q = 0; q < 4; q++) d[mb][nb][q] = 0.0f;

    const uint32_t aBase = smb +
        (uint32_t)(((mw * 64 + (lane & 15)) * AST + ((lane >> 4) & 1) * 8) * 2);
    const uint32_t bBase = smb + PRJ_B +
        (uint32_t)(((nw * 32 + (lane & 7)) * AST + (lane & 8)) * 2);

    for (int kc = 0; kc < 4; ++kc) {
#pragma unroll
        for (int q = 0; q < 8; ++q) {
            const int i = tid + q * 256;
            const int term = i >> 10, idx = i & 1023;
            const int r = idx >> 3, cq = idx & 7;
            const uint4 v = *(const uint4*)
                &g_xbf[term][mt * 128 + r][kc * 64 + cq * 8];
            *(uint4*)(smc + (term * PA_TERM + r * AST + cq * 8) * 2) = v;
        }
#pragma unroll
        for (int q = 0; q < 8; ++q) {
            const int i = tid + q * 256;
            const int term = i >> 10, idx = i & 1023;
            const int r = idx >> 3, cq = idx & 7;
            const uint4 v = *(const uint4*)
                &g_wbf[dir][term][nt * 128 + r][kc * 64 + cq * 8];
            *(uint4*)(smc + PRJ_B + (term * PA_TERM + r * AST + cq * 8) * 2) = v;
        }
        __syncthreads();

#pragma unroll
        for (int k16 = 0; k16 < 4; ++k16) {
            const uint32_t ko = (uint32_t)(k16 * 16 * 2);
            uint32_t bh[4][2], bl[4][2];
#pragma unroll
            for (int nb = 0; nb < 4; ++nb) {
                const uint32_t ba = bBase + (uint32_t)(nb * 8 * AST * 2) + ko;
                ldsm2(bh[nb][0], bh[nb][1], ba);
                ldsm2(bl[nb][0], bl[nb][1], ba + PA_TERM * 2);
            }
#pragma unroll
            for (int mb = 0; mb < 4; ++mb) {
                uint32_t ah[4], al[4];
                const uint32_t aa = aBase + (uint32_t)(mb * 16 * AST * 2) + ko;
                ldsm4(ah, aa);
                ldsm4(al, aa + PA_TERM * 2);
#pragma unroll
                for (int nb = 0; nb < 4; ++nb) {
                    mma16816(d[mb][nb], ah, bh[nb][0], bh[nb][1]);
                    mma16816(d[mb][nb], ah, bl[nb][0], bl[nb][1]);
                    mma16816(d[mb][nb], al, bh[nb][0], bh[nb][1]);
                }
            }
        }
        __syncthreads();
    }

    const int r = lane >> 2, c2 = (lane & 3) * 2;
#pragma unroll
    for (int nb = 0; nb < 4; ++nb) {
        const int col = nt * 128 + nw * 32 + nb * 8 + c2;
        const float2 bv = *(const float2*)(bias + col);
#pragma unroll
        for (int mb = 0; mb < 4; ++mb) {
            const int row = mt * 128 + mw * 64 + mb * 16 + r;
            *(float2*)&g_xw[dir][row][col] =
                make_float2(d[mb][nb][0] + bv.x, d[mb][nb][1] + bv.y);
            *(float2*)&g_xw[dir][row + 8][col] =
                make_float2(d[mb][nb][2] + bv.x, d[mb][nb][3] + bv.y);
        }
    }
}

// ---------------- persistent tensor recurrence ----------------------------
// 512 threads, 16 warps. K split: warps 0-7 -> K[0,256), warps 8-15 ->
// K[256,512). Thread group g (tid>>8) copies its own K-half via cp.async and
// syncs on named barrier 1+g, so the two halves copy+compute in parallel.
#define HSTR 520
#define HS_HI 0
#define HS_LO 66560
#define US_HI 133120
#define US_LO 166400
#define ZB0   199680         // float zb0[64][34]
#define ZB1   208384         // float zb1[64][34]
#define SMEM_TOTAL 217088

__global__ __launch_bounds__(512, 1) void lstm_persistent(
    const float* __restrict__ Uf, const float* __restrict__ Ub,
    float* __restrict__ dout) {
    extern __shared__ char smc[];
    const uint32_t smb = s2u(smc);
    float* zb0 = (float*)(smc + ZB0);
    float* zb1 = (float*)(smc + ZB1);

    const int dir = blockIdx.y;
    const int jt  = blockIdx.x;
    const int j0  = jt * 8;
    const int cid = dir * 64 + jt;
    const int tid = threadIdx.x;
    const int w   = tid >> 5;
    const int lane = tid & 31;
    const int grp = tid >> 8;          // K-half group (0/1)
    const int lt  = tid & 255;

    // ---- resident U slice as bf16 hi/lo, [n=32][k=512] row-major ----
    const float* U = dir ? Ub : Uf;
    for (int i = tid; i < 32 * 512; i += 512) {
        const int n = i >> 9, k = i & 511;
        const int gcol = ((n >> 3) << 9) + j0 + (n & 7);
        const float v = U[(size_t)k * G4H + gcol];
        const __nv_bfloat16 hi = __float2bfloat16_rn(v);
        const __nv_bfloat16 lo = __float2bfloat16_rn(v - __bfloat162float(hi));
        *(__nv_bfloat16*)(smc + US_HI + (n * HSTR + k) * 2) = hi;
        *(__nv_bfloat16*)(smc + US_LO + (n * HSTR + k) * 2) = lo;
    }

    // MMA roles within the K-half: 8 warps -> 4 m-blocks x 2 n-pairs
    const int wi  = w & 7;
    const int mb  = wi >> 1;
    const int nb0 = (wi & 1) * 2;
    const uint32_t aoff = (uint32_t)(((mb * 16 + (lane & 15)) * HSTR +
                                      ((lane >> 4) & 1) * 8) * 2);
    const uint32_t aHi = smb + HS_HI + aoff;
    const uint32_t aLo = smb + HS_LO + aoff;
    const uint32_t boff = (uint32_t)(((nb0 * 8 + (lane & 7)) * HSTR +
                                      (lane & 8)) * 2);
    const uint32_t b0Hi = smb + US_HI + boff;
    const uint32_t b1Hi = b0Hi + 8 * HSTR * 2;
    const uint32_t b0Lo = smb + US_LO + boff;
    const uint32_t b1Lo = b0Lo + 8 * HSTR * 2;
    const uint32_t kbase = (uint32_t)(grp * 256 * 2);
    float* zbme = grp ? zb1 : zb0;

    // epilogue role: thread = (batch b, unit-pair up), tid < 256
    const int eb = tid >> 2;
    const int up = (tid & 3) * 2;

    const float* xw = &g_xw[dir][0][0];

    float creg[2] = {0.0f, 0.0f};

    __syncthreads();  // U ready

    for (int s = 0; s < TT; ++s) {
        // ---- distributed flag barrier: wait for all CTAs at step s ----
        if (tid < NCTA) {
            volatile unsigned* fl = g_flags;
            while (fl[tid] < (unsigned)s) { }
        }
        __syncthreads();

        const int pr = s & 1;
        const int t = dir ? (TT - 1 - s) : s;

        // ---- cp.async copy of OWN K-half (64KB by 256 threads) ----
        {
            const uint4* src = (const uint4*)&g_hbf[dir][pr][0][0][0];
#pragma unroll
            for (int q = 0; q < 16; ++q) {
                const int i = lt + q * 256;        // 0..4095
                const int m = i >> 11;             // plane hi/lo
                const int r = (i >> 5) & 63;
                const int c16 = i & 31;
                cpasync16(smb + (m ? HS_LO : HS_HI) +
                              (uint32_t)((r * HSTR + grp * 256 + c16 * 8) * 2),
                          src + (m * 4096 + r * 64 + grp * 32 + c16));
            }
            CP_COMMIT();
        }

        // ---- epilogue operand prefetch (tid<256: thread = (b, up)) ----
        float xg[4][2];
        if (tid < 256) {
            const float* xrow = xw + (size_t)(eb * TT + t) * G4H + j0 + up;
#pragma unroll
            for (int g = 0; g < 4; g++) {
                const float2 a = *(const float2*)(xrow + g * 512);
                xg[g][0] = a.x; xg[g][1] = a.y;
            }
        }

        // ---- own half landed? sync only within the 256-thread group ----
        CP_WAIT(0);
        if (grp == 0) asm volatile("bar.sync 1, 256;" ::: "memory");
        else          asm volatile("bar.sync 2, 256;" ::: "memory");

        // ---- tensor GEMM on own K-half: 16 chunks x 6 MMA ----
        float d0[4] = {0.f, 0.f, 0.f, 0.f};
        float d1[4] = {0.f, 0.f, 0.f, 0.f};
#pragma unroll 4
        for (int k0 = 0; k0 < 256; k0 += 16) {
            const uint32_t ko = kbase + (uint32_t)(k0 * 2);
            uint32_t ah[4], al[4], bh0[2], bh1[2], bl0[2], bl1[2];
            ldsm4(ah, aHi + ko);
            ldsm2(bh0[0], bh0[1], b0Hi + ko);
            ldsm2(bh1[0], bh1[1], b1Hi + ko);
            ldsm2(bl0[0], bl0[1], b0Lo + ko);
            ldsm2(bl1[0], bl1[1], b1Lo + ko);
            ldsm4(al, aLo + ko);
            mma16816(d0, ah, bh0[0], bh0[1]);
            mma16816(d1, ah, bh1[0], bh1[1]);
            mma16816(d0, ah, bl0[0], bl0[1]);
            mma16816(d1, ah, bl1[0], bl1[1]);
            mma16816(d0, al, bh0[0], bh0[1]);
            mma16816(d1, al, bh1[0], bh1[1]);
        }

        // ---- store partials to own zb slice ----
        {
            const int r0 = mb * 16 + (lane >> 2);
            const int c0 = nb0 * 8 + 2 * (lane & 3);
            zbme[r0 * 34 + c0]           = d0[0];
            zbme[r0 * 34 + c0 + 1]       = d0[1];
            zbme[(r0 + 8) * 34 + c0]     = d0[2];
            zbme[(r0 + 8) * 34 + c0 + 1] = d0[3];
            zbme[r0 * 34 + c0 + 8]           = d1[0];
            zbme[r0 * 34 + c0 + 9]           = d1[1];
            zbme[(r0 + 8) * 34 + c0 + 8]     = d1[2];
            zbme[(r0 + 8) * 34 + c0 + 9]     = d1[3];
        }
        __syncthreads();

        // ---- fused gates + cell update + stores (256 threads) ----
        if (tid < 256) {
            const int b = eb;
            float hv[2];
#pragma unroll
            for (int j = 0; j < 2; j++) {
                const int jj = up + j;
                const float zi = zb0[b * 34 + jj]      + zb1[b * 34 + jj]      + xg[0][j];
                const float zf = zb0[b * 34 + 8 + jj]  + zb1[b * 34 + 8 + jj]  + xg[1][j];
                const float zg = zb0[b * 34 + 16 + jj] + zb1[b * 34 + 16 + jj] + xg[2][j];
                const float zo = zb0[b * 34 + 24 + jj] + zb1[b * 34 + 24 + jj] + xg[3][j];
                const float ig = sigm(zi), fg = sigm(zf);
                const float gg = sigm(zg), og = sigm(zo);
                const float cn = fg * creg[j] + ig * gg;
                creg[j] = cn;
                hv[j] = og * sigm(cn);
            }
            uint32_t hiw, low;
            split_pack(hv[0], hv[1], hiw, low);
            *(uint32_t*)&g_hbf[dir][pr ^ 1][0][b][j0 + up] = hiw;
            *(uint32_t*)&g_hbf[dir][pr ^ 1][1][b][j0 + up] = low;

            // direct output: first writer (s<256) stores, second accumulates.
            float* dp = dout + ((size_t)b * TT + t) * HH + j0 + up;
            float2 o = make_float2(0.5f * hv[0], 0.5f * hv[1]);
            if (s >= 256) {
                const float2 p = __ldcg((const float2*)dp);
                o.x += p.x; o.y += p.y;
            }
            *(float2*)dp = o;

            if (s == TT - 1) {   // final states straight to output
                float* hf = dout + OUT0 + dir * 65536 + b * HH + j0 + up;
                float* cf = hf + 32768;
                *(float2*)hf = make_float2(hv[0], hv[1]);
                *(float2*)cf = make_float2(creg[0], creg[1]);
            }
        }

        // ---- publish + arrive: own flag, distinct address per CTA ----
        __threadfence();
        __syncthreads();
        if (tid == 0) atomicExch(&g_flags[cid], (unsigned)(s + 1));
    }
}

// ---------------- launch ---------------------------------------------------
extern "C" void kernel_launch(void* const* d_in, const int* in_sizes, int n_in,
                              void* d_out, int out_size) {
    const float* x  = (const float*)d_in[0];
    // d_in[1] = hidden : unused by the reference (zero initial state)
    const float* Wf = (const float*)d_in[2];
    const float* Uf = (const float*)d_in[3];
    const float* bf = (const float*)d_in[4];
    const float* Wb = (const float*)d_in[5];
    const float* Ub = (const float*)d_in[6];
    const float* bb = (const float*)d_in[7];
    float* out = (float*)d_out;

    cudaFuncSetAttribute(lstm_persistent,
                         cudaFuncAttributeMaxDynamicSharedMemorySize, SMEM_TOTAL);
    cudaFuncSetAttribute(proj_mma_kernel,
                         cudaFuncAttributeMaxDynamicSharedMemorySize, PRJ_SMEM);

    // re-zero recurrent state + flags every launch (graph replay safe)
    init_state_kernel<<<512, 256>>>();

    // bf16 hi/lo conversion of x and W (transposed)
    convert_x_kernel<<<MROWS * DD / 2 / 256, 256>>>(x);
    convert_w_kernel<<<dim3(G4H / 32, DD / 32, 2), dim3(32, 32)>>>(Wf, Wb);

    // tensor-core input projection for both directions
    proj_mma_kernel<<<dim3(MROWS / 128, G4H / 128, 2), 256, PRJ_SMEM>>>(bf, bb);

    // persistent tensor-core recurrence: one kernel, 512 steps, flag barrier
    lstm_persistent<<<dim3(64, 2), 512, SMEM_TOTAL>>>(Uf, Ub, out);
}

// round 17
// speedup vs baseline: 3.0021x; 1.0712x over previous
#include <cuda_runtime.h>
#include <cuda_bf16.h>
#include <cstdint>

// Shapes (fixed)
#define BB 64
#define TT 512
#define DD 256
#define HH 512
#define G4H 2048           // 4*H
#define MROWS 32768        // B*T
#define OUT0 16777216      // B*T*H
#define NCTA_DIR 64        // CTAs per direction

// ---------------- device scratch ------------------------------------------
__device__ float g_xw[2][MROWS][G4H];               // x@W+b, row r = b*T + t
__device__ float g_hout[2][BB][TT][HH];             // per-direction hidden seq
__device__ __nv_bfloat16 g_hbf[2][2][2][BB][HH];    // [dir][pingpong][hi/lo][b][k]
__device__ __nv_bfloat16 g_xbf[2][MROWS][DD];       // [hi/lo][row][k]
__device__ __nv_bfloat16 g_wbf[2][2][G4H][DD];      // [dir][hi/lo][n][k]
__device__ unsigned g_flags[2][NCTA_DIR];           // per-direction barrier flags

__device__ __forceinline__ float sigm(float x) {
    return 1.0f / (1.0f + __expf(-x));
}

__device__ __forceinline__ uint32_t s2u(const void* p) {
    uint32_t a;
    asm("{ .reg .u64 t; cvta.to.shared.u64 t, %1; cvt.u32.u64 %0, t; }"
        : "=r"(a) : "l"(p));
    return a;
}

// ---- warp-level tensor ops (sm_80-baseline PTX; works on compute_103) ----
__device__ __forceinline__ void ldsm4(uint32_t* a, uint32_t addr) {
    asm volatile("ldmatrix.sync.aligned.m8n8.x4.shared.b16 {%0,%1,%2,%3}, [%4];"
                 : "=r"(a[0]), "=r"(a[1]), "=r"(a[2]), "=r"(a[3]) : "r"(addr));
}
__device__ __forceinline__ void ldsm2(uint32_t& b0, uint32_t& b1, uint32_t addr) {
    asm volatile("ldmatrix.sync.aligned.m8n8.x2.shared.b16 {%0,%1}, [%2];"
                 : "=r"(b0), "=r"(b1) : "r"(addr));
}
__device__ __forceinline__ void mma16816(float* d, const uint32_t* a,
                                         uint32_t b0, uint32_t b1) {
    asm volatile(
        "mma.sync.aligned.m16n8k16.row.col.f32.bf16.bf16.f32 "
        "{%0,%1,%2,%3}, {%4,%5,%6,%7}, {%8,%9}, {%0,%1,%2,%3};"
        : "+f"(d[0]), "+f"(d[1]), "+f"(d[2]), "+f"(d[3])
        : "r"(a[0]), "r"(a[1]), "r"(a[2]), "r"(a[3]), "r"(b0), "r"(b1));
}

__device__ __forceinline__ void cpasync16(uint32_t dst, const void* src) {
    asm volatile("cp.async.cg.shared.global [%0], [%1], 16;"
                 :: "r"(dst), "l"(src) : "memory");
}
#define CP_COMMIT() asm volatile("cp.async.commit_group;" ::: "memory")
#define CP_WAIT(n)  asm volatile("cp.async.wait_group %0;" :: "n"(n) : "memory")

__device__ __forceinline__ void split_pack(float v0, float v1,
                                           uint32_t& hiw, uint32_t& low) {
    const __nv_bfloat16 h0 = __float2bfloat16_rn(v0);
    const __nv_bfloat16 h1 = __float2bfloat16_rn(v1);
    const __nv_bfloat16 l0 = __float2bfloat16_rn(v0 - __bfloat162float(h0));
    const __nv_bfloat16 l1 = __float2bfloat16_rn(v1 - __bfloat162float(h1));
    hiw = (uint32_t)__bfloat16_as_ushort(h0) |
          ((uint32_t)__bfloat16_as_ushort(h1) << 16);
    low = (uint32_t)__bfloat16_as_ushort(l0) |
          ((uint32_t)__bfloat16_as_ushort(l1) << 16);
}

// ---------------- state init (replay-safe) --------------------------------
__global__ void init_state_kernel() {
    int i = blockIdx.x * blockDim.x + threadIdx.x;   // 131072 threads
    ((uint32_t*)&g_hbf[0][0][0][0][0])[i] = 0u;      // 512KB of bf16 zeros
    if (i < 2 * NCTA_DIR) g_flags[0][i] = 0u;
}

// ---------------- convert x -> bf16 hi/lo planes --------------------------
__global__ void convert_x_kernel(const float* __restrict__ x) {
    const int i = blockIdx.x * 256 + threadIdx.x;    // MROWS*DD/2 pairs
    const float2 v = ((const float2*)x)[i];
    uint32_t hiw, low;
    split_pack(v.x, v.y, hiw, low);
    ((uint32_t*)&g_xbf[0][0][0])[i] = hiw;
    ((uint32_t*)&g_xbf[1][0][0])[i] = low;
}

// ---------------- convert + transpose W -> g_wbf[dir][term][n][k] ---------
__global__ void convert_w_kernel(const float* __restrict__ Wf,
                                 const float* __restrict__ Wb) {
    __shared__ float tile[32][33];
    const float* W = blockIdx.z ? Wb : Wf;
    const int n0 = blockIdx.x * 32, k0 = blockIdx.y * 32;
    tile[threadIdx.y][threadIdx.x] =
        W[(size_t)(k0 + threadIdx.y) * G4H + n0 + threadIdx.x];
    __syncthreads();
    const int n = n0 + threadIdx.y, k = k0 + threadIdx.x;
    const float v = tile[threadIdx.x][threadIdx.y];
    const __nv_bfloat16 hi = __float2bfloat16_rn(v);
    const __nv_bfloat16 lo = __float2bfloat16_rn(v - __bfloat162float(hi));
    g_wbf[blockIdx.z][0][n][k] = hi;
    g_wbf[blockIdx.z][1][n][k] = lo;
}

// ---------------- tensor projection: g_xw = x @ W + b ---------------------
// CTA tile 128x128, K=256 in 4 chunks of 64, cp.async DOUBLE-BUFFERED.
// 8 warps (2x4), warp 64x32. 3 bf16 terms: xhi*whi + xhi*wlo + xlo*whi.
#define AST 72                      // smem stride in halfs (144B)
#define PA_TERM (128 * AST)         // halfs per term plane = 9216
#define PRJ_BOFF (2 * PA_TERM * 2)  // B planes offset within a stage = 36864
#define PRJ_STAGE 73728             // bytes per stage (A 36864 + B 36864)
#define PRJ_SMEM (2 * PRJ_STAGE)    // 147456

__global__ __launch_bounds__(256, 1) void proj_mma_kernel(
    const float* __restrict__ bf, const float* __restrict__ bb) {
    extern __shared__ char smc[];
    const uint32_t smb = s2u(smc);

    const int mt = blockIdx.x, nt = blockIdx.y, dir = blockIdx.z;
    const float* bias = dir ? bb : bf;
    const int tid = threadIdx.x;
    const int w = tid >> 5, lane = tid & 31;
    const int mw = w >> 2, nw = w & 3;

    float d[4][4][4];
#pragma unroll
    for (int mb = 0; mb < 4; mb++)
#pragma unroll
        for (int nb = 0; nb < 4; nb++)
#pragma unroll
            for (int q = 0; q < 4; q++) d[mb][nb][q] = 0.0f;

    // per-thread loader coords (A and B use the same mapping)
    const int lterm = tid >> 7;            // with q*256: i = tid+q*256
    (void)lterm;
    const uint32_t aOff =
        (uint32_t)(((mw * 64 + (lane & 15)) * AST + ((lane >> 4) & 1) * 8) * 2);
    const uint32_t bOff = (uint32_t)PRJ_BOFF +
        (uint32_t)(((nw * 32 + (lane & 7)) * AST + (lane & 8)) * 2);

    // stage loader: issue 16 cp.async per thread (8 A + 8 B)
    auto load_stage = [&](int kc, int stage) {
        const uint32_t sb = smb + (uint32_t)(stage * PRJ_STAGE);
#pragma unroll
        for (int q = 0; q < 8; ++q) {
            const int i = tid + q * 256;
            const int term = i >> 10, idx = i & 1023;
            const int r = idx >> 3, cq = idx & 7;
            cpasync16(sb + (uint32_t)((term * PA_TERM + r * AST + cq * 8) * 2),
                      &g_xbf[term][mt * 128 + r][kc * 64 + cq * 8]);
        }
#pragma unroll
        for (int q = 0; q < 8; ++q) {
            const int i = tid + q * 256;
            const int term = i >> 10, idx = i & 1023;
            const int r = idx >> 3, cq = idx & 7;
            cpasync16(sb + (uint32_t)PRJ_BOFF +
                          (uint32_t)((term * PA_TERM + r * AST + cq * 8) * 2),
                      &g_wbf[dir][term][nt * 128 + r][kc * 64 + cq * 8]);
        }
        CP_COMMIT();
    };

    load_stage(0, 0);

    for (int kc = 0; kc < 4; ++kc) {
        const int st = kc & 1;
        if (kc < 3) { load_stage(kc + 1, st ^ 1); CP_WAIT(1); }
        else        { CP_WAIT(0); }
        __syncthreads();

        const uint32_t aBase = smb + (uint32_t)(st * PRJ_STAGE) + aOff;
        const uint32_t bBase = smb + (uint32_t)(st * PRJ_STAGE) + bOff;
#pragma unroll
        for (int k16 = 0; k16 < 4; ++k16) {
            const uint32_t ko = (uint32_t)(k16 * 16 * 2);
            uint32_t bh[4][2], bl[4][2];
#pragma unroll
            for (int nb = 0; nb < 4; ++nb) {
                const uint32_t ba = bBase + (uint32_t)(nb * 8 * AST * 2) + ko;
                ldsm2(bh[nb][0], bh[nb][1], ba);
                ldsm2(bl[nb][0], bl[nb][1], ba + PA_TERM * 2);
            }
#pragma unroll
            for (int mb = 0; mb < 4; ++mb) {
                uint32_t ah[4], al[4];
                const uint32_t aa = aBase + (uint32_t)(mb * 16 * AST * 2) + ko;
                ldsm4(ah, aa);
                ldsm4(al, aa + PA_TERM * 2);
#pragma unroll
                for (int nb = 0; nb < 4; ++nb) {
                    mma16816(d[mb][nb], ah, bh[nb][0], bh[nb][1]);
                    mma16816(d[mb][nb], ah, bl[nb][0], bl[nb][1]);
                    mma16816(d[mb][nb], al, bh[nb][0], bh[nb][1]);
                }
            }
        }
        __syncthreads();   // stage consumed; safe to overwrite next iteration
    }

    const int r = lane >> 2, c2 = (lane & 3) * 2;
#pragma unroll
    for (int nb = 0; nb < 4; ++nb) {
        const int col = nt * 128 + nw * 32 + nb * 8 + c2;
        const float2 bv = *(const float2*)(bias + col);
#pragma unroll
        for (int mb = 0; mb < 4; ++mb) {
            const int row = mt * 128 + mw * 64 + mb * 16 + r;
            *(float2*)&g_xw[dir][row][col] =
                make_float2(d[mb][nb][0] + bv.x, d[mb][nb][1] + bv.y);
            *(float2*)&g_xw[dir][row + 8][col] =
                make_float2(d[mb][nb][2] + bv.x, d[mb][nb][3] + bv.y);
        }
    }
}

// ---------------- persistent tensor recurrence ----------------------------
// 512 threads, 16 warps, K split 2x256 with per-group named barriers.
// PER-DIRECTION flag barrier (64 CTAs) — directions fully decoupled.
#define HSTR 520
#define HS_HI 0
#define HS_LO 66560
#define US_HI 133120
#define US_LO 166400
#define ZB0   199680         // float zb0[64][34]
#define ZB1   208384         // float zb1[64][34]
#define SMEM_TOTAL 217088

__global__ __launch_bounds__(512, 1) void lstm_persistent(
    const float* __restrict__ Uf, const float* __restrict__ Ub,
    float* __restrict__ dout) {
    extern __shared__ char smc[];
    const uint32_t smb = s2u(smc);
    float* zb0 = (float*)(smc + ZB0);
    float* zb1 = (float*)(smc + ZB1);

    const int dir = blockIdx.y;
    const int jt  = blockIdx.x;
    const int j0  = jt * 8;
    const int tid = threadIdx.x;
    const int w   = tid >> 5;
    const int lane = tid & 31;
    const int grp = tid >> 8;          // K-half group (0/1)
    const int lt  = tid & 255;

    // ---- resident U slice as bf16 hi/lo, [n=32][k=512] row-major ----
    const float* U = dir ? Ub : Uf;
    for (int i = tid; i < 32 * 512; i += 512) {
        const int n = i >> 9, k = i & 511;
        const int gcol = ((n >> 3) << 9) + j0 + (n & 7);
        const float v = U[(size_t)k * G4H + gcol];
        const __nv_bfloat16 hi = __float2bfloat16_rn(v);
        const __nv_bfloat16 lo = __float2bfloat16_rn(v - __bfloat162float(hi));
        *(__nv_bfloat16*)(smc + US_HI + (n * HSTR + k) * 2) = hi;
        *(__nv_bfloat16*)(smc + US_LO + (n * HSTR + k) * 2) = lo;
    }

    // MMA roles within the K-half: 8 warps -> 4 m-blocks x 2 n-pairs
    const int wi  = w & 7;
    const int mb  = wi >> 1;
    const int nb0 = (wi & 1) * 2;
    const uint32_t aoff = (uint32_t)(((mb * 16 + (lane & 15)) * HSTR +
                                      ((lane >> 4) & 1) * 8) * 2);
    const uint32_t aHi = smb + HS_HI + aoff;
    const uint32_t aLo = smb + HS_LO + aoff;
    const uint32_t boff = (uint32_t)(((nb0 * 8 + (lane & 7)) * HSTR +
                                      (lane & 8)) * 2);
    const uint32_t b0Hi = smb + US_HI + boff;
    const uint32_t b1Hi = b0Hi + 8 * HSTR * 2;
    const uint32_t b0Lo = smb + US_LO + boff;
    const uint32_t b1Lo = b0Lo + 8 * HSTR * 2;
    const uint32_t kbase = (uint32_t)(grp * 256 * 2);
    float* zbme = grp ? zb1 : zb0;

    // epilogue role: thread = (batch b, unit-pair up), tid < 256
    const int eb = tid >> 2;
    const int up = (tid & 3) * 2;

    const float* xw = &g_xw[dir][0][0];
    float* hout = &g_hout[dir][0][0][0];
    volatile unsigned* fl = g_flags[dir];

    float creg[2] = {0.0f, 0.0f};

    __syncthreads();  // U ready

    for (int s = 0; s < TT; ++s) {
        // ---- per-direction flag barrier: wait for own 64 CTAs ----
        if (tid < NCTA_DIR) {
            while (fl[tid] < (unsigned)s) { }
        }
        __syncthreads();

        const int pr = s & 1;
        const int t = dir ? (TT - 1 - s) : s;

        // ---- cp.async copy of OWN K-half (64KB by 256 threads) ----
        {
            const uint4* src = (const uint4*)&g_hbf[dir][pr][0][0][0];
#pragma unroll
            for (int q = 0; q < 16; ++q) {
                const int i = lt + q * 256;        // 0..4095
                const int m = i >> 11;             // plane hi/lo
                const int r = (i >> 5) & 63;
                const int c16 = i & 31;
                cpasync16(smb + (m ? HS_LO : HS_HI) +
                              (uint32_t)((r * HSTR + grp * 256 + c16 * 8) * 2),
                          src + (m * 4096 + r * 64 + grp * 32 + c16));
            }
            CP_COMMIT();
        }

        // ---- epilogue operand prefetch (tid<256: thread = (b, up)) ----
        float xg[4][2];
        if (tid < 256) {
            const float* xrow = xw + (size_t)(eb * TT + t) * G4H + j0 + up;
#pragma unroll
            for (int g = 0; g < 4; g++) {
                const float2 a = *(const float2*)(xrow + g * 512);
                xg[g][0] = a.x; xg[g][1] = a.y;
            }
        }

        // ---- own half landed? sync only within the 256-thread group ----
        CP_WAIT(0);
        if (grp == 0) asm volatile("bar.sync 1, 256;" ::: "memory");
        else          asm volatile("bar.sync 2, 256;" ::: "memory");

        // ---- tensor GEMM on own K-half: 16 chunks x 6 MMA ----
        float d0[4] = {0.f, 0.f, 0.f, 0.f};
        float d1[4] = {0.f, 0.f, 0.f, 0.f};
#pragma unroll 4
        for (int k0 = 0; k0 < 256; k0 += 16) {
            const uint32_t ko = kbase + (uint32_t)(k0 * 2);
            uint32_t ah[4], al[4], bh0[2], bh1[2], bl0[2], bl1[2];
            ldsm4(ah, aHi + ko);
            ldsm2(bh0[0], bh0[1], b0Hi + ko);
            ldsm2(bh1[0], bh1[1], b1Hi + ko);
            ldsm2(bl0[0], bl0[1], b0Lo + ko);
            ldsm2(bl1[0], bl1[1], b1Lo + ko);
            ldsm4(al, aLo + ko);
            mma16816(d0, ah, bh0[0], bh0[1]);
            mma16816(d1, ah, bh1[0], bh1[1]);
            mma16816(d0, ah, bl0[0], bl0[1]);
            mma16816(d1, ah, bl1[0], bl1[1]);
            mma16816(d0, al, bh0[0], bh0[1]);
            mma16816(d1, al, bh1[0], bh1[1]);
        }

        // ---- store partials to own zb slice ----
        {
            const int r0 = mb * 16 + (lane >> 2);
            const int c0 = nb0 * 8 + 2 * (lane & 3);
            zbme[r0 * 34 + c0]           = d0[0];
            zbme[r0 * 34 + c0 + 1]       = d0[1];
            zbme[(r0 + 8) * 34 + c0]     = d0[2];
            zbme[(r0 + 8) * 34 + c0 + 1] = d0[3];
            zbme[r0 * 34 + c0 + 8]           = d1[0];
            zbme[r0 * 34 + c0 + 9]           = d1[1];
            zbme[(r0 + 8) * 34 + c0 + 8]     = d1[2];
            zbme[(r0 + 8) * 34 + c0 + 9]     = d1[3];
        }
        __syncthreads();

        // ---- fused gates + cell update + stores (256 threads) ----
        if (tid < 256) {
            const int b = eb;
            float hv[2];
#pragma unroll
            for (int j = 0; j < 2; j++) {
                const int jj = up + j;
                const float zi = zb0[b * 34 + jj]      + zb1[b * 34 + jj]      + xg[0][j];
                const float zf = zb0[b * 34 + 8 + jj]  + zb1[b * 34 + 8 + jj]  + xg[1][j];
                const float zg = zb0[b * 34 + 16 + jj] + zb1[b * 34 + 16 + jj] + xg[2][j];
                const float zo = zb0[b * 34 + 24 + jj] + zb1[b * 34 + 24 + jj] + xg[3][j];
                const float ig = sigm(zi), fg = sigm(zf);
                const float gg = sigm(zg), og = sigm(zo);
                const float cn = fg * creg[j] + ig * gg;
                creg[j] = cn;
                hv[j] = og * sigm(cn);
            }
            uint32_t hiw, low;
            split_pack(hv[0], hv[1], hiw, low);
            *(uint32_t*)&g_hbf[dir][pr ^ 1][0][b][j0 + up] = hiw;
            *(uint32_t*)&g_hbf[dir][pr ^ 1][1][b][j0 + up] = low;

            // per-direction hidden sequence (no cross-direction RMW)
            *(float2*)(hout + ((size_t)b * TT + t) * HH + j0 + up) =
                make_float2(hv[0], hv[1]);

            if (s == TT - 1) {   // final states straight to output
                float* hf = dout + OUT0 + dir * 65536 + b * HH + j0 + up;
                float* cf = hf + 32768;
                *(float2*)hf = make_float2(hv[0], hv[1]);
                *(float2*)cf = make_float2(creg[0], creg[1]);
            }
        }

        // ---- publish + arrive: own flag, distinct address per CTA ----
        __threadfence();
        __syncthreads();
        if (tid == 0) atomicExch((unsigned*)&g_flags[dir][jt], (unsigned)(s + 1));
    }
}

// ---------------- combine: out = 0.5*(h_f + h_b) ---------------------------
__global__ void combine_kernel(float* __restrict__ dout) {
    const int i = blockIdx.x * 256 + threadIdx.x;   // OUT0/4 float4 elems
    const float4 a = ((const float4*)&g_hout[0][0][0][0])[i];
    const float4 b = ((const float4*)&g_hout[1][0][0][0])[i];
    ((float4*)dout)[i] = make_float4(0.5f * (a.x + b.x), 0.5f * (a.y + b.y),
                                     0.5f * (a.z + b.z), 0.5f * (a.w + b.w));
}

// ---------------- launch ---------------------------------------------------
extern "C" void kernel_launch(void* const* d_in, const int* in_sizes, int n_in,
                              void* d_out, int out_size) {
    const float* x  = (const float*)d_in[0];
    // d_in[1] = hidden : unused by the reference (zero initial state)
    const float* Wf = (const float*)d_in[2];
    const float* Uf = (const float*)d_in[3];
    const float* bf = (const float*)d_in[4];
    const float* Wb = (const float*)d_in[5];
    const float* Ub = (const float*)d_in[6];
    const float* bb = (const float*)d_in[7];
    float* out = (float*)d_out;

    cudaFuncSetAttribute(lstm_persistent,
                         cudaFuncAttributeMaxDynamicSharedMemorySize, SMEM_TOTAL);
    cudaFuncSetAttribute(proj_mma_kernel,
                         cudaFuncAttributeMaxDynamicSharedMemorySize, PRJ_SMEM);

    // re-zero recurrent state + flags every launch (graph replay safe)
    init_state_kernel<<<512, 256>>>();

    // bf16 hi/lo conversion of x and W (transposed)
    convert_x_kernel<<<MROWS * DD / 2 / 256, 256>>>(x);
    convert_w_kernel<<<dim3(G4H / 32, DD / 32, 2), dim3(32, 32)>>>(Wf, Wb);

    // tensor-core input projection (cp.async double-buffered)
    proj_mma_kernel<<<dim3(MROWS / 128, G4H / 128, 2), 256, PRJ_SMEM>>>(bf, bb);

    // persistent tensor-core recurrence: per-direction flag barrier
    lstm_persistent<<<dim3(NCTA_DIR, 2), 512, SMEM_TOTAL>>>(Uf, Ub, out);

    // blend directions
    combine_kernel<<<OUT0 / 4 / 256, 256>>>(out);
}